// round 2
// baseline (speedup 1.0000x reference)
#include <cuda_runtime.h>
#include <cstdint>
#include <cstddef>

#define B_ 2
#define N_ 50000
#define E_ 500000
#define D_ 128
#define O_ 128
#define K_ 384
#define M_ (B_*N_)

typedef unsigned long long ull;

// Scratch (device globals: no allocation allowed in kernel_launch)
__device__ float g_XS[(size_t)B_ * N_ * D_];   // per-dst sum of x[b, src] (51.2 MB)
__device__ float g_EA[(size_t)N_ * D_];        // per-dst sum of edge_attr (25.6 MB)
__device__ int   g_icnt[N_];                   // in-degree counts
__device__ int   g_off[N_ + 1];                // CSR offsets by dst
__device__ int   g_pos[N_];                    // running fill cursor
__device__ int   g_esrc[E_];                   // src node of sorted edge
__device__ int   g_eidx[E_];                   // original edge id of sorted edge
__device__ float g_Wc[K_ * O_];                // W_msg @ W_upd
__device__ float g_bmu[O_];                    // b_msg @ W_upd

// ---------------------------------------------------------------------------
// f32x2 packed helpers (sm_103a dual-rate fp32 pipe; FFMA2 only via PTX)
// ---------------------------------------------------------------------------
__device__ __forceinline__ ull pack2(float lo, float hi) {
    ull r; asm("mov.b64 %0, {%1, %2};" : "=l"(r) : "f"(lo), "f"(hi)); return r;
}
__device__ __forceinline__ float2 unpack2(ull v) {
    float2 f; asm("mov.b64 {%0, %1}, %2;" : "=f"(f.x), "=f"(f.y) : "l"(v)); return f;
}
#define FMA2(d, a, b) \
    asm("fma.rn.f32x2 %0, %1, %2, %0;" : "+l"(d) : "l"(a), "l"(b))

// ---------------------------------------------------------------------------
// CSR build: histogram -> scan -> bucket fill
// ---------------------------------------------------------------------------
__global__ void zero_icnt() {
    int i = blockIdx.x * blockDim.x + threadIdx.x;
    if (i < N_) g_icnt[i] = 0;
}

__global__ void hist_kernel(const int* __restrict__ ei) {
    int e = blockIdx.x * blockDim.x + threadIdx.x;
    if (e < E_) atomicAdd(&g_icnt[ei[E_ + e]], 1);
}

__global__ void scan_kernel() {
    __shared__ int ssum[1024];
    const int CH = (N_ + 1023) / 1024;   // 49
    int t = threadIdx.x;
    int beg = t * CH, end = min(beg + CH, N_);
    int s = 0;
    for (int i = beg; i < end; ++i) s += g_icnt[i];
    ssum[t] = s;
    __syncthreads();
    // Hillis-Steele inclusive scan over 1024 partials
    for (int off = 1; off < 1024; off <<= 1) {
        int v = (t >= off) ? ssum[t - off] : 0;
        __syncthreads();
        ssum[t] += v;
        __syncthreads();
    }
    int run = (t == 0) ? 0 : ssum[t - 1];   // exclusive base
    for (int i = beg; i < end; ++i) {
        g_off[i] = run;
        g_pos[i] = run;
        run += g_icnt[i];
    }
    if (t == 1023) g_off[N_] = run;
}

__global__ void fill_kernel(const int* __restrict__ ei) {
    int e = blockIdx.x * blockDim.x + threadIdx.x;
    if (e < E_) {
        int dst = ei[E_ + e];
        int p = atomicAdd(&g_pos[dst], 1);
        g_esrc[p] = ei[e];
        g_eidx[p] = e;
    }
}

// ---------------------------------------------------------------------------
// Gather-sum aggregation: one warp per node, lane l handles channels [4l,4l+4).
// No atomics; writes every node's rows (zeros for degree-0 nodes).
// ---------------------------------------------------------------------------
__global__ void aggregate(const float* __restrict__ x,
                          const float* __restrict__ ea) {
    int n = (int)(((size_t)blockIdx.x * blockDim.x + threadIdx.x) >> 5);
    int lane = threadIdx.x & 31;
    if (n >= N_) return;

    int j0 = g_off[n], j1 = g_off[n + 1];
    float4 aea = make_float4(0.f, 0.f, 0.f, 0.f);
    float4 ax0 = aea, ax1 = aea;

    for (int j = j0; j < j1; ++j) {
        int src = g_esrc[j];
        int e   = g_eidx[j];
        float4 va = reinterpret_cast<const float4*>(ea + (size_t)e * D_)[lane];
        float4 v0 = reinterpret_cast<const float4*>(x + (size_t)src * D_)[lane];
        float4 v1 = reinterpret_cast<const float4*>(x + ((size_t)N_ + src) * D_)[lane];
        aea.x += va.x; aea.y += va.y; aea.z += va.z; aea.w += va.w;
        ax0.x += v0.x; ax0.y += v0.y; ax0.z += v0.z; ax0.w += v0.w;
        ax1.x += v1.x; ax1.y += v1.y; ax1.z += v1.z; ax1.w += v1.w;
    }

    reinterpret_cast<float4*>(g_EA + (size_t)n * D_)[lane] = aea;
    reinterpret_cast<float4*>(g_XS + (size_t)n * D_)[lane] = ax0;
    reinterpret_cast<float4*>(g_XS + ((size_t)N_ + n) * D_)[lane] = ax1;
}

// ---------------------------------------------------------------------------
// W_comb = W_msg @ W_upd  (384x128 @ 128x128), bmu = b_msg @ W_upd
// ---------------------------------------------------------------------------
__global__ void combine_weights(const float* __restrict__ Wm,
                                const float* __restrict__ Wu,
                                const float* __restrict__ bm) {
    int idx = blockIdx.x * blockDim.x + threadIdx.x;
    if (idx < K_ * O_) {
        int k = idx >> 7;
        int o = idx & 127;
        float s = 0.f;
        #pragma unroll 8
        for (int j = 0; j < O_; ++j)
            s = fmaf(Wm[k * O_ + j], Wu[j * O_ + o], s);
        g_Wc[idx] = s;
    }
    if (idx < O_) {
        float s = 0.f;
        for (int j = 0; j < O_; ++j)
            s = fmaf(bm[j], Wu[j * O_ + idx], s);
        g_bmu[idx] = s;
    }
}

// ---------------------------------------------------------------------------
// Fused node GEMM with packed f32x2 FFMA (dual-rate fp32):
//   A[r] = [ inv(r)*g_XS[r] , cc(r)*x[r] , inv(r)*g_EA[r%N] ]   (row of 384)
//   out[r] = A[r] @ W_comb + cc(r)*bmu + b_upd
// 128x128 block tile, BK=8, 256 threads, 8x8 microtile, double buffered.
// A is stored DUPLICATED in smem (each value at 2m, 2m+1) so the inner loop
// reads broadcast pairs directly as u64 — no per-k packing movs.
// ---------------------------------------------------------------------------
__global__ __launch_bounds__(256, 2)
void fused_gemm(const float* __restrict__ x,
                const float* __restrict__ bu,
                float* __restrict__ out)
{
    __shared__ float As[2][8][256];   // duplicated rows: 16 KB
    __shared__ float Bs[2][8][128];   // 8 KB
    __shared__ float inv_s[128], cc_s[128], bmu_s[128], bu_s[128];

    const int tid = threadIdx.x;
    const int r0  = blockIdx.x * 128;
    const int tx  = tid & 15;
    const int ty  = tid >> 4;

    if (tid < 128) {
        int r = r0 + tid;
        float inv = 0.f, cc = 0.f;
        if (r < M_) {
            int n = (r >= N_) ? (r - N_) : r;
            float c = (float)g_icnt[n];
            inv = 1.0f / fmaxf(c, 1.0f);
            cc  = (c > 0.f) ? 1.f : 0.f;
        }
        inv_s[tid] = inv;
        cc_s[tid]  = cc;
        bmu_s[tid] = g_bmu[tid];
        bu_s[tid]  = bu[tid];
    }
    __syncthreads();

    // A-tile loader: 128 rows x 8 cols = 256 float4, one per thread.
    auto loadA = [&](int kb, float4& v, float& sc, int& m, int& kc) {
        m      = tid >> 1;
        int jj = tid & 1;
        int phase = kb >> 7;                 // 0: XS, 1: x, 2: EA
        int kof4  = ((kb & 127) >> 2) + jj;
        int r  = r0 + m;
        int rc = (r < M_) ? r : (M_ - 1);
        const float* base;
        if (phase == 0)      base = g_XS + (size_t)rc * 128;
        else if (phase == 1) base = x    + (size_t)rc * 128;
        else {
            int n = (rc >= N_) ? (rc - N_) : rc;
            base = g_EA + (size_t)n * 128;
        }
        v  = reinterpret_cast<const float4*>(base)[kof4];
        sc = (phase == 1) ? cc_s[m] : inv_s[m];
        kc = jj * 4;
    };
    auto storeA = [&](int buf, const float4& v, float sc, int m, int kc) {
        *reinterpret_cast<ull*>(&As[buf][kc + 0][2 * m]) = pack2(v.x * sc, v.x * sc);
        *reinterpret_cast<ull*>(&As[buf][kc + 1][2 * m]) = pack2(v.y * sc, v.y * sc);
        *reinterpret_cast<ull*>(&As[buf][kc + 2][2 * m]) = pack2(v.z * sc, v.z * sc);
        *reinterpret_cast<ull*>(&As[buf][kc + 3][2 * m]) = pack2(v.w * sc, v.w * sc);
    };
    // B-tile loader: 8 rows x 128 cols = 256 float4, one per thread.
    auto loadB = [&](int kb, float4& v, int& kr, int& c4) {
        kr     = tid >> 5;
        int cg = tid & 31;
        v  = reinterpret_cast<const float4*>(g_Wc + (size_t)(kb + kr) * 128)[cg];
        c4 = cg * 4;
    };

    // Prologue: tile 0 into buffer 0
    {
        float4 av, bv; float sc; int m, kc, kr, c4;
        loadA(0, av, sc, m, kc);
        storeA(0, av, sc, m, kc);
        loadB(0, bv, kr, c4);
        *reinterpret_cast<float4*>(&Bs[0][kr][c4]) = bv;
    }
    __syncthreads();

    ull acc2[8][4];
    #pragma unroll
    for (int i = 0; i < 8; ++i)
        #pragma unroll
        for (int j = 0; j < 4; ++j) acc2[i][j] = 0ull;

    const int NT = K_ / 8;  // 48
    for (int kt = 0; kt < NT; ++kt) {
        int cur = kt & 1;

        float4 av, bv; float sc; int am, akc, bkr, bc4;
        if (kt + 1 < NT) {
            loadA((kt + 1) * 8, av, sc, am, akc);
            loadB((kt + 1) * 8, bv, bkr, bc4);
        }

        #pragma unroll
        for (int k = 0; k < 8; ++k) {
            const ull* arow = reinterpret_cast<const ull*>(&As[cur][k][0]); // 128 dup-pairs
            const ull* brow = reinterpret_cast<const ull*>(&Bs[cur][k][0]); // 64 col-pairs
            ulonglong2 A0 = *reinterpret_cast<const ulonglong2*>(&arow[ty * 4]);
            ulonglong2 A1 = *reinterpret_cast<const ulonglong2*>(&arow[ty * 4 + 2]);
            ulonglong2 A2 = *reinterpret_cast<const ulonglong2*>(&arow[64 + ty * 4]);
            ulonglong2 A3 = *reinterpret_cast<const ulonglong2*>(&arow[64 + ty * 4 + 2]);
            ulonglong2 B0 = *reinterpret_cast<const ulonglong2*>(&brow[tx * 2]);
            ulonglong2 B1 = *reinterpret_cast<const ulonglong2*>(&brow[32 + tx * 2]);
            ull a[8] = {A0.x, A0.y, A1.x, A1.y, A2.x, A2.y, A3.x, A3.y};
            ull b[4] = {B0.x, B0.y, B1.x, B1.y};
            #pragma unroll
            for (int i = 0; i < 8; ++i) {
                FMA2(acc2[i][0], a[i], b[0]);
                FMA2(acc2[i][1], a[i], b[1]);
                FMA2(acc2[i][2], a[i], b[2]);
                FMA2(acc2[i][3], a[i], b[3]);
            }
        }

        if (kt + 1 < NT) {
            int nb = cur ^ 1;
            storeA(nb, av, sc, am, akc);
            *reinterpret_cast<float4*>(&Bs[nb][bkr][bc4]) = bv;
            __syncthreads();
        }
    }

    // Epilogue
    #pragma unroll
    for (int i = 0; i < 8; ++i) {
        int m = (i < 4) ? (ty * 4 + i) : (64 + ty * 4 + (i - 4));
        int r = r0 + m;
        if (r < M_) {
            float ccb = cc_s[m];
            int n0 = tx * 4, n1 = 64 + tx * 4;
            float2 p0 = unpack2(acc2[i][0]);
            float2 p1 = unpack2(acc2[i][1]);
            float2 p2 = unpack2(acc2[i][2]);
            float2 p3 = unpack2(acc2[i][3]);
            float4 v0, v1;
            v0.x = p0.x + ccb * bmu_s[n0 + 0] + bu_s[n0 + 0];
            v0.y = p0.y + ccb * bmu_s[n0 + 1] + bu_s[n0 + 1];
            v0.z = p1.x + ccb * bmu_s[n0 + 2] + bu_s[n0 + 2];
            v0.w = p1.y + ccb * bmu_s[n0 + 3] + bu_s[n0 + 3];
            v1.x = p2.x + ccb * bmu_s[n1 + 0] + bu_s[n1 + 0];
            v1.y = p2.y + ccb * bmu_s[n1 + 1] + bu_s[n1 + 1];
            v1.z = p3.x + ccb * bmu_s[n1 + 2] + bu_s[n1 + 2];
            v1.w = p3.y + ccb * bmu_s[n1 + 3] + bu_s[n1 + 3];
            *reinterpret_cast<float4*>(&out[(size_t)r * 128 + n0]) = v0;
            *reinterpret_cast<float4*>(&out[(size_t)r * 128 + n1]) = v1;
        }
    }
}

// ---------------------------------------------------------------------------
// Launch
// ---------------------------------------------------------------------------
extern "C" void kernel_launch(void* const* d_in, const int* in_sizes, int n_in,
                              void* d_out, int out_size) {
    const float* x  = (const float*)d_in[0];   // (B, N, D)
    const int*   ei = (const int*)  d_in[1];   // (2, E)
    const float* ea = (const float*)d_in[2];   // (E, D)
    const float* Wm = (const float*)d_in[3];   // (3D, O)
    const float* bm = (const float*)d_in[4];   // (O,)
    const float* Wu = (const float*)d_in[5];   // (O, O)
    const float* bu = (const float*)d_in[6];   // (O,)
    float* out = (float*)d_out;                // (B, N, O)

    zero_icnt<<<(N_ + 255) / 256, 256>>>();
    hist_kernel<<<(E_ + 255) / 256, 256>>>(ei);
    scan_kernel<<<1, 1024>>>();
    fill_kernel<<<(E_ + 255) / 256, 256>>>(ei);
    combine_weights<<<(K_ * O_ + 255) / 256, 256>>>(Wm, Wu, bm);
    aggregate<<<(int)(((size_t)N_ * 32 + 255) / 256), 256>>>(x, ea);
    fused_gemm<<<(M_ + 127) / 128, 256>>>(x, bu, out);
}

// round 3
// speedup vs baseline: 1.0729x; 1.0729x over previous
#include <cuda_runtime.h>
#include <cstdint>
#include <cstddef>

#define B_ 2
#define N_ 50000
#define E_ 500000
#define D_ 128
#define O_ 128
#define K_ 384
#define M_ (B_*N_)

// Scratch (device globals: no allocation allowed in kernel_launch)
__device__ float g_XS[(size_t)B_ * N_ * D_];   // per-dst sum of x[b, src] (51.2 MB)
__device__ float g_EA[(size_t)N_ * D_];        // per-dst sum of edge_attr (25.6 MB)
__device__ int   g_icnt[N_];                   // in-degree counts
__device__ int   g_off[N_ + 1];                // CSR offsets by dst
__device__ int   g_pos[N_];                    // running fill cursor
__device__ int2  g_edge[E_];                   // (src, original edge id), sorted by dst
__device__ float g_Wc[K_ * O_];                // W_msg @ W_upd
__device__ float g_bmu[O_];                    // b_msg @ W_upd

// ---------------------------------------------------------------------------
// CSR build: histogram -> scan -> bucket fill
// ---------------------------------------------------------------------------
__global__ void zero_icnt() {
    int i = blockIdx.x * blockDim.x + threadIdx.x;
    if (i < N_) g_icnt[i] = 0;
}

__global__ void hist_kernel(const int* __restrict__ ei) {
    int e = blockIdx.x * blockDim.x + threadIdx.x;
    if (e < E_) atomicAdd(&g_icnt[ei[E_ + e]], 1);
}

__global__ void scan_kernel() {
    __shared__ int ssum[1024];
    const int CH = (N_ + 1023) / 1024;   // 49
    int t = threadIdx.x;
    int beg = t * CH, end = min(beg + CH, N_);
    int s = 0;
    for (int i = beg; i < end; ++i) s += g_icnt[i];
    ssum[t] = s;
    __syncthreads();
    for (int off = 1; off < 1024; off <<= 1) {
        int v = (t >= off) ? ssum[t - off] : 0;
        __syncthreads();
        ssum[t] += v;
        __syncthreads();
    }
    int run = (t == 0) ? 0 : ssum[t - 1];   // exclusive base
    for (int i = beg; i < end; ++i) {
        g_off[i] = run;
        g_pos[i] = run;
        run += g_icnt[i];
    }
    if (t == 1023) g_off[N_] = run;
}

__global__ void fill_kernel(const int* __restrict__ ei) {
    int e = blockIdx.x * blockDim.x + threadIdx.x;
    if (e < E_) {
        int dst = ei[E_ + e];
        int p = atomicAdd(&g_pos[dst], 1);
        g_edge[p] = make_int2(ei[e], e);
    }
}

// ---------------------------------------------------------------------------
// Gather-sum aggregation: one warp per node, lane l handles channels [4l,4l+4).
// 2-edge unrolled for MLP (6 independent 512B row loads in flight).
// ---------------------------------------------------------------------------
__global__ void aggregate(const float* __restrict__ x,
                          const float* __restrict__ ea) {
    int n = (int)(((size_t)blockIdx.x * blockDim.x + threadIdx.x) >> 5);
    int lane = threadIdx.x & 31;
    if (n >= N_) return;

    int j0 = g_off[n], j1 = g_off[n + 1];
    float4 aea = make_float4(0.f, 0.f, 0.f, 0.f);
    float4 ax0 = aea, ax1 = aea;
    float4 bea = aea, bx0 = aea, bx1 = aea;

    int j = j0;
    for (; j + 2 <= j1; j += 2) {
        int2 p0 = g_edge[j];
        int2 p1 = g_edge[j + 1];
        float4 va0 = reinterpret_cast<const float4*>(ea + (size_t)p0.y * D_)[lane];
        float4 va1 = reinterpret_cast<const float4*>(ea + (size_t)p1.y * D_)[lane];
        float4 u0  = reinterpret_cast<const float4*>(x + (size_t)p0.x * D_)[lane];
        float4 u1  = reinterpret_cast<const float4*>(x + (size_t)p1.x * D_)[lane];
        float4 w0  = reinterpret_cast<const float4*>(x + ((size_t)N_ + p0.x) * D_)[lane];
        float4 w1  = reinterpret_cast<const float4*>(x + ((size_t)N_ + p1.x) * D_)[lane];
        aea.x += va0.x; aea.y += va0.y; aea.z += va0.z; aea.w += va0.w;
        bea.x += va1.x; bea.y += va1.y; bea.z += va1.z; bea.w += va1.w;
        ax0.x += u0.x;  ax0.y += u0.y;  ax0.z += u0.z;  ax0.w += u0.w;
        bx0.x += u1.x;  bx0.y += u1.y;  bx0.z += u1.z;  bx0.w += u1.w;
        ax1.x += w0.x;  ax1.y += w0.y;  ax1.z += w0.z;  ax1.w += w0.w;
        bx1.x += w1.x;  bx1.y += w1.y;  bx1.z += w1.z;  bx1.w += w1.w;
    }
    if (j < j1) {
        int2 p0 = g_edge[j];
        float4 va = reinterpret_cast<const float4*>(ea + (size_t)p0.y * D_)[lane];
        float4 u  = reinterpret_cast<const float4*>(x + (size_t)p0.x * D_)[lane];
        float4 w  = reinterpret_cast<const float4*>(x + ((size_t)N_ + p0.x) * D_)[lane];
        aea.x += va.x; aea.y += va.y; aea.z += va.z; aea.w += va.w;
        ax0.x += u.x;  ax0.y += u.y;  ax0.z += u.z;  ax0.w += u.w;
        ax1.x += w.x;  ax1.y += w.y;  ax1.z += w.z;  ax1.w += w.w;
    }
    aea.x += bea.x; aea.y += bea.y; aea.z += bea.z; aea.w += bea.w;
    ax0.x += bx0.x; ax0.y += bx0.y; ax0.z += bx0.z; ax0.w += bx0.w;
    ax1.x += bx1.x; ax1.y += bx1.y; ax1.z += bx1.z; ax1.w += bx1.w;

    reinterpret_cast<float4*>(g_EA + (size_t)n * D_)[lane] = aea;
    reinterpret_cast<float4*>(g_XS + (size_t)n * D_)[lane] = ax0;
    reinterpret_cast<float4*>(g_XS + ((size_t)N_ + n) * D_)[lane] = ax1;
}

// ---------------------------------------------------------------------------
// W_comb = W_msg @ W_upd  (384x128 @ 128x128), bmu = b_msg @ W_upd
// ---------------------------------------------------------------------------
__global__ void combine_weights(const float* __restrict__ Wm,
                                const float* __restrict__ Wu,
                                const float* __restrict__ bm) {
    int idx = blockIdx.x * blockDim.x + threadIdx.x;
    if (idx < K_ * O_) {
        int k = idx >> 7;
        int o = idx & 127;
        float s = 0.f;
        #pragma unroll 8
        for (int j = 0; j < O_; ++j)
            s = fmaf(Wm[k * O_ + j], Wu[j * O_ + o], s);
        g_Wc[idx] = s;
    }
    if (idx < O_) {
        float s = 0.f;
        for (int j = 0; j < O_; ++j)
            s = fmaf(bm[j], Wu[j * O_ + idx], s);
        g_bmu[idx] = s;
    }
}

// ---------------------------------------------------------------------------
// Fused node GEMM (round-1 proven version):
//   A[r] = [ inv(r)*g_XS[r] , cc(r)*x[r] , inv(r)*g_EA[r%N] ]   (row of 384)
//   out[r] = A[r] @ W_comb + cc(r)*bmu + b_upd
// 128x128 block tile, BK=16, 256 threads, 8x8 microtile, double buffered.
// ---------------------------------------------------------------------------
__global__ __launch_bounds__(256, 2)
void fused_gemm(const float* __restrict__ x,
                const float* __restrict__ bu,
                float* __restrict__ out)
{
    __shared__ float As[2][16][128];
    __shared__ float Bs[2][16][128];
    __shared__ float inv_s[128], cc_s[128], bmu_s[128], bu_s[128];

    const int tid = threadIdx.x;
    const int r0  = blockIdx.x * 128;
    const int tx  = tid & 15;
    const int ty  = tid >> 4;

    if (tid < 128) {
        int r = r0 + tid;
        float inv = 0.f, cc = 0.f;
        if (r < M_) {
            int n = (r >= N_) ? (r - N_) : r;
            float c = (float)g_icnt[n];
            inv = 1.0f / fmaxf(c, 1.0f);
            cc  = (c > 0.f) ? 1.f : 0.f;
        }
        inv_s[tid] = inv;
        cc_s[tid]  = cc;
        bmu_s[tid] = g_bmu[tid];
        bu_s[tid]  = bu[tid];
    }
    __syncthreads();

    // A-tile loader: 128 rows x 16 cols = 512 float4, 2 per thread.
    auto loadA = [&](int kb, int s, float4& v, float& sc, int& m, int& kc) {
        int f  = tid + s * 256;
        m      = f >> 2;
        int jj = f & 3;
        int phase = kb >> 7;                 // 0: XS(src), 1: x(dst), 2: EA
        int kof4  = ((kb & 127) >> 2) + jj;  // float4 index within source row
        int r  = r0 + m;
        int rc = (r < M_) ? r : (M_ - 1);
        const float* base;
        if (phase == 0)      base = g_XS + (size_t)rc * 128;
        else if (phase == 1) base = x    + (size_t)rc * 128;
        else {
            int n = (rc >= N_) ? (rc - N_) : rc;
            base = g_EA + (size_t)n * 128;
        }
        v  = reinterpret_cast<const float4*>(base)[kof4];
        sc = (phase == 1) ? cc_s[m] : inv_s[m];
        kc = jj * 4;
    };
    // B-tile loader: 16 rows x 128 cols of W_comb, 2 float4 per thread.
    auto loadB = [&](int kb, int s, float4& v, int& kr, int& c4) {
        int f  = tid + s * 256;
        kr     = f >> 5;
        int cg = f & 31;
        v  = reinterpret_cast<const float4*>(g_Wc + (size_t)(kb + kr) * 128)[cg];
        c4 = cg * 4;
    };

    // Prologue: tile 0 into buffer 0
    {
        float4 av, bv; float sc; int m, kc, kr, c4;
        #pragma unroll
        for (int s = 0; s < 2; ++s) {
            loadA(0, s, av, sc, m, kc);
            As[0][kc + 0][m] = av.x * sc;
            As[0][kc + 1][m] = av.y * sc;
            As[0][kc + 2][m] = av.z * sc;
            As[0][kc + 3][m] = av.w * sc;
            loadB(0, s, bv, kr, c4);
            *reinterpret_cast<float4*>(&Bs[0][kr][c4]) = bv;
        }
    }
    __syncthreads();

    float acc[8][8];
    #pragma unroll
    for (int i = 0; i < 8; ++i)
        #pragma unroll
        for (int j = 0; j < 8; ++j) acc[i][j] = 0.f;

    const int NT = K_ / 16;  // 24
    for (int kt = 0; kt < NT; ++kt) {
        int cur = kt & 1;

        float4 av[2], bv[2]; float sc[2];
        int am[2], akc[2], bkr[2], bc4[2];
        if (kt + 1 < NT) {
            #pragma unroll
            for (int s = 0; s < 2; ++s) {
                loadA((kt + 1) * 16, s, av[s], sc[s], am[s], akc[s]);
                loadB((kt + 1) * 16, s, bv[s], bkr[s], bc4[s]);
            }
        }

        #pragma unroll
        for (int k = 0; k < 16; ++k) {
            float4 a0 = *reinterpret_cast<const float4*>(&As[cur][k][ty * 4]);
            float4 a1 = *reinterpret_cast<const float4*>(&As[cur][k][ty * 4 + 64]);
            float4 b0 = *reinterpret_cast<const float4*>(&Bs[cur][k][tx * 4]);
            float4 b1 = *reinterpret_cast<const float4*>(&Bs[cur][k][tx * 4 + 64]);
            float a[8] = {a0.x, a0.y, a0.z, a0.w, a1.x, a1.y, a1.z, a1.w};
            float b[8] = {b0.x, b0.y, b0.z, b0.w, b1.x, b1.y, b1.z, b1.w};
            #pragma unroll
            for (int i = 0; i < 8; ++i)
                #pragma unroll
                for (int j = 0; j < 8; ++j)
                    acc[i][j] = fmaf(a[i], b[j], acc[i][j]);
        }

        if (kt + 1 < NT) {
            int nb = cur ^ 1;
            #pragma unroll
            for (int s = 0; s < 2; ++s) {
                As[nb][akc[s] + 0][am[s]] = av[s].x * sc[s];
                As[nb][akc[s] + 1][am[s]] = av[s].y * sc[s];
                As[nb][akc[s] + 2][am[s]] = av[s].z * sc[s];
                As[nb][akc[s] + 3][am[s]] = av[s].w * sc[s];
                *reinterpret_cast<float4*>(&Bs[nb][bkr[s]][bc4[s]]) = bv[s];
            }
            __syncthreads();
        }
    }

    // Epilogue
    #pragma unroll
    for (int i = 0; i < 8; ++i) {
        int m = (i < 4) ? (ty * 4 + i) : (64 + ty * 4 + (i - 4));
        int r = r0 + m;
        if (r < M_) {
            float ccb = cc_s[m];
            int n0 = tx * 4, n1 = 64 + tx * 4;
            float4 v0, v1;
            v0.x = acc[i][0] + ccb * bmu_s[n0 + 0] + bu_s[n0 + 0];
            v0.y = acc[i][1] + ccb * bmu_s[n0 + 1] + bu_s[n0 + 1];
            v0.z = acc[i][2] + ccb * bmu_s[n0 + 2] + bu_s[n0 + 2];
            v0.w = acc[i][3] + ccb * bmu_s[n0 + 3] + bu_s[n0 + 3];
            v1.x = acc[i][4] + ccb * bmu_s[n1 + 0] + bu_s[n1 + 0];
            v1.y = acc[i][5] + ccb * bmu_s[n1 + 1] + bu_s[n1 + 1];
            v1.z = acc[i][6] + ccb * bmu_s[n1 + 2] + bu_s[n1 + 2];
            v1.w = acc[i][7] + ccb * bmu_s[n1 + 3] + bu_s[n1 + 3];
            *reinterpret_cast<float4*>(&out[(size_t)r * 128 + n0]) = v0;
            *reinterpret_cast<float4*>(&out[(size_t)r * 128 + n1]) = v1;
        }
    }
}

// ---------------------------------------------------------------------------
// Launch
// ---------------------------------------------------------------------------
extern "C" void kernel_launch(void* const* d_in, const int* in_sizes, int n_in,
                              void* d_out, int out_size) {
    const float* x  = (const float*)d_in[0];   // (B, N, D)
    const int*   ei = (const int*)  d_in[1];   // (2, E)
    const float* ea = (const float*)d_in[2];   // (E, D)
    const float* Wm = (const float*)d_in[3];   // (3D, O)
    const float* bm = (const float*)d_in[4];   // (O,)
    const float* Wu = (const float*)d_in[5];   // (O, O)
    const float* bu = (const float*)d_in[6];   // (O,)
    float* out = (float*)d_out;                // (B, N, O)

    zero_icnt<<<(N_ + 255) / 256, 256>>>();
    hist_kernel<<<(E_ + 255) / 256, 256>>>(ei);
    scan_kernel<<<1, 1024>>>();
    fill_kernel<<<(E_ + 255) / 256, 256>>>(ei);
    combine_weights<<<(K_ * O_ + 255) / 256, 256>>>(Wm, Wu, bm);
    aggregate<<<(int)(((size_t)N_ * 32 + 255) / 256), 256>>>(x, ea);
    fused_gemm<<<(M_ + 127) / 128, 256>>>(x, bu, out);
}

// round 5
// speedup vs baseline: 1.1977x; 1.1164x over previous
#include <cuda_runtime.h>
#include <cuda_bf16.h>
#include <cstdint>
#include <cstddef>

#define B_ 2
#define N_ 50000
#define E_ 500000
#define D_ 128
#define O_ 128
#define K_ 384
#define M_ (B_*N_)

// ---------------------------------------------------------------------------
// Device scratch (no allocation allowed in kernel_launch)
// ---------------------------------------------------------------------------
__device__ float g_XS[(size_t)B_ * N_ * D_];   // per-dst sum of x[b, src]
__device__ float g_EA[(size_t)N_ * D_];        // per-dst sum of edge_attr
__device__ int   g_icnt[N_];                   // in-degree counts
__device__ int   g_off[N_ + 1];                // CSR offsets by dst
__device__ int   g_pos[N_];                    // fill cursor
__device__ int2  g_edge[E_];                   // (src, edge id) sorted by dst
__device__ __nv_bfloat16 g_Bhi[O_ * K_];       // (W_msg@W_upd)^T hi, [n][k]
__device__ __nv_bfloat16 g_Blo[O_ * K_];       // (W_msg@W_upd)^T lo, [n][k]
__device__ float g_bmu[O_];                    // b_msg @ W_upd

// ---------------------------------------------------------------------------
// mma.sync bf16 (sm_80-era PTX — compiles on plain compute_103)
// acc(f32x4) += A(16x16 bf16, 4 regs) @ B(16x8 bf16, 2 regs)
// ---------------------------------------------------------------------------
#define MMA_BF16(d, a, b)                                                     \
    asm volatile("mma.sync.aligned.m16n8k16.row.col.f32.bf16.bf16.f32 "       \
        "{%0,%1,%2,%3}, {%4,%5,%6,%7}, {%8,%9}, {%0,%1,%2,%3};"               \
        : "+f"((d)[0]), "+f"((d)[1]), "+f"((d)[2]), "+f"((d)[3])              \
        : "r"((a)[0]), "r"((a)[1]), "r"((a)[2]), "r"((a)[3]),                 \
          "r"((b)[0]), "r"((b)[1]))

// Split 8 fp32 (two float4) into packed bf16 hi + lo (uint4 each).
__device__ __forceinline__ void split8(float4 f0, float4 f1, uint4& h, uint4& l) {
    float v[8] = {f0.x, f0.y, f0.z, f0.w, f1.x, f1.y, f1.z, f1.w};
    uint32_t hs[8], ls[8];
    #pragma unroll
    for (int i = 0; i < 8; ++i) {
        __nv_bfloat16 hb = __float2bfloat16_rn(v[i]);
        float r = v[i] - __bfloat162float(hb);
        __nv_bfloat16 lb = __float2bfloat16_rn(r);
        hs[i] = (uint32_t)__bfloat16_as_ushort(hb);
        ls[i] = (uint32_t)__bfloat16_as_ushort(lb);
    }
    h = make_uint4(hs[0] | (hs[1] << 16), hs[2] | (hs[3] << 16),
                   hs[4] | (hs[5] << 16), hs[6] | (hs[7] << 16));
    l = make_uint4(ls[0] | (ls[1] << 16), ls[2] | (ls[3] << 16),
                   ls[4] | (ls[5] << 16), ls[6] | (ls[7] << 16));
}

// ---------------------------------------------------------------------------
// CSR build: histogram -> scan -> bucket fill (unchanged)
// ---------------------------------------------------------------------------
__global__ void zero_icnt() {
    int i = blockIdx.x * blockDim.x + threadIdx.x;
    if (i < N_) g_icnt[i] = 0;
}

__global__ void hist_kernel(const int* __restrict__ ei) {
    int e = blockIdx.x * blockDim.x + threadIdx.x;
    if (e < E_) atomicAdd(&g_icnt[ei[E_ + e]], 1);
}

__global__ void scan_kernel() {
    __shared__ int ssum[1024];
    const int CH = (N_ + 1023) / 1024;
    int t = threadIdx.x;
    int beg = t * CH, end = min(beg + CH, N_);
    int s = 0;
    for (int i = beg; i < end; ++i) s += g_icnt[i];
    ssum[t] = s;
    __syncthreads();
    for (int off = 1; off < 1024; off <<= 1) {
        int v = (t >= off) ? ssum[t - off] : 0;
        __syncthreads();
        ssum[t] += v;
        __syncthreads();
    }
    int run = (t == 0) ? 0 : ssum[t - 1];
    for (int i = beg; i < end; ++i) {
        g_off[i] = run;
        g_pos[i] = run;
        run += g_icnt[i];
    }
    if (t == 1023) g_off[N_] = run;
}

__global__ void fill_kernel(const int* __restrict__ ei) {
    int e = blockIdx.x * blockDim.x + threadIdx.x;
    if (e < E_) {
        int dst = ei[E_ + e];
        int p = atomicAdd(&g_pos[dst], 1);
        g_edge[p] = make_int2(ei[e], e);
    }
}

// ---------------------------------------------------------------------------
// Gather-sum aggregation (unchanged)
// ---------------------------------------------------------------------------
__global__ void aggregate(const float* __restrict__ x,
                          const float* __restrict__ ea) {
    int n = (int)(((size_t)blockIdx.x * blockDim.x + threadIdx.x) >> 5);
    int lane = threadIdx.x & 31;
    if (n >= N_) return;

    int j0 = g_off[n], j1 = g_off[n + 1];
    float4 aea = make_float4(0.f, 0.f, 0.f, 0.f);
    float4 ax0 = aea, ax1 = aea;
    float4 bea = aea, bx0 = aea, bx1 = aea;

    int j = j0;
    for (; j + 2 <= j1; j += 2) {
        int2 p0 = g_edge[j];
        int2 p1 = g_edge[j + 1];
        float4 va0 = reinterpret_cast<const float4*>(ea + (size_t)p0.y * D_)[lane];
        float4 va1 = reinterpret_cast<const float4*>(ea + (size_t)p1.y * D_)[lane];
        float4 u0  = reinterpret_cast<const float4*>(x + (size_t)p0.x * D_)[lane];
        float4 u1  = reinterpret_cast<const float4*>(x + (size_t)p1.x * D_)[lane];
        float4 w0  = reinterpret_cast<const float4*>(x + ((size_t)N_ + p0.x) * D_)[lane];
        float4 w1  = reinterpret_cast<const float4*>(x + ((size_t)N_ + p1.x) * D_)[lane];
        aea.x += va0.x; aea.y += va0.y; aea.z += va0.z; aea.w += va0.w;
        bea.x += va1.x; bea.y += va1.y; bea.z += va1.z; bea.w += va1.w;
        ax0.x += u0.x;  ax0.y += u0.y;  ax0.z += u0.z;  ax0.w += u0.w;
        bx0.x += u1.x;  bx0.y += u1.y;  bx0.z += u1.z;  bx0.w += u1.w;
        ax1.x += w0.x;  ax1.y += w0.y;  ax1.z += w0.z;  ax1.w += w0.w;
        bx1.x += w1.x;  bx1.y += w1.y;  bx1.z += w1.z;  bx1.w += w1.w;
    }
    if (j < j1) {
        int2 p0 = g_edge[j];
        float4 va = reinterpret_cast<const float4*>(ea + (size_t)p0.y * D_)[lane];
        float4 u  = reinterpret_cast<const float4*>(x + (size_t)p0.x * D_)[lane];
        float4 w  = reinterpret_cast<const float4*>(x + ((size_t)N_ + p0.x) * D_)[lane];
        aea.x += va.x; aea.y += va.y; aea.z += va.z; aea.w += va.w;
        ax0.x += u.x;  ax0.y += u.y;  ax0.z += u.z;  ax0.w += u.w;
        ax1.x += w.x;  ax1.y += w.y;  ax1.z += w.z;  ax1.w += w.w;
    }
    aea.x += bea.x; aea.y += bea.y; aea.z += bea.z; aea.w += bea.w;
    ax0.x += bx0.x; ax0.y += bx0.y; ax0.z += bx0.z; ax0.w += bx0.w;
    ax1.x += bx1.x; ax1.y += bx1.y; ax1.z += bx1.z; ax1.w += bx1.w;

    reinterpret_cast<float4*>(g_EA + (size_t)n * D_)[lane] = aea;
    reinterpret_cast<float4*>(g_XS + (size_t)n * D_)[lane] = ax0;
    reinterpret_cast<float4*>(g_XS + ((size_t)N_ + n) * D_)[lane] = ax1;
}

// ---------------------------------------------------------------------------
// Combined weights, transposed + bf16 hi/lo split:
//   Wc[k][o] = sum_j Wm[k][j]*Wu[j][o];  g_Bhi/lo[o][k] = split(Wc[k][o])
// ---------------------------------------------------------------------------
__global__ void combine_weights(const float* __restrict__ Wm,
                                const float* __restrict__ Wu,
                                const float* __restrict__ bm) {
    int idx = blockIdx.x * blockDim.x + threadIdx.x;
    if (idx < K_ * O_) {
        int o = idx / K_;
        int k = idx - o * K_;
        float s = 0.f;
        #pragma unroll 8
        for (int j = 0; j < O_; ++j)
            s = fmaf(Wm[k * O_ + j], Wu[j * O_ + o], s);
        __nv_bfloat16 hb = __float2bfloat16_rn(s);
        float r = s - __bfloat162float(hb);
        g_Bhi[idx] = hb;
        g_Blo[idx] = __float2bfloat16_rn(r);
    }
    if (idx < O_) {
        float s = 0.f;
        for (int j = 0; j < O_; ++j)
            s = fmaf(bm[j], Wu[j * O_ + idx], s);
        g_bmu[idx] = s;
    }
}

// ---------------------------------------------------------------------------
// Tensor-core fused GEMM via mma.sync bf16, hi/lo split (3 passes):
//   A[r] = [ inv*XS[r] , cc*x[r] , inv*EA[r%N] ]  (384 fp32)
//   out[r] = A[r] @ Wc + cc*bmu + b_upd
// CTA tile 64x128, BK=32, 256 thr (8 warps = 2(m)x4(n)), warp tile 32x32.
// Smem rows padded to 40 bf16 -> conflict-free .b32 frag loads.
// ---------------------------------------------------------------------------
#define STR_ 40                      // bf16 per smem row
#define ASZ_ (64 * STR_ * 2)         // bytes per A buffer (5120)
#define BSZ_ (128 * STR_ * 2)        // bytes per B buffer (10240)
#define AH_OFF 0
#define AL_OFF (2 * ASZ_)            // 10240
#define BH_OFF (4 * ASZ_)            // 20480
#define BL_OFF (4 * ASZ_ + 2 * BSZ_) // 40960
#define SMEM_DYN_ (4 * ASZ_ + 4 * BSZ_)  // 61440

__global__ __launch_bounds__(256, 2)
void fused_gemm_mma(const float* __restrict__ x,
                    const float* __restrict__ bu,
                    float* __restrict__ out)
{
    extern __shared__ char sm[];
    __shared__ float inv_s[64], cc_s[64], bmu_s[128], bu_s[128];

    const int tid  = threadIdx.x;
    const int lane = tid & 31;
    const int wid  = tid >> 5;
    const int r0   = blockIdx.x * 64;
    const int wm   = wid >> 2;        // 0..1
    const int wn   = wid & 3;         // 0..3
    const int g    = lane >> 2;       // 0..7
    const int tq   = lane & 3;        // 0..3

    if (tid < 64) {
        int r = r0 + tid;
        float inv = 0.f, cc = 0.f;
        if (r < M_) {
            int n = (r >= N_) ? (r - N_) : r;
            float c = (float)g_icnt[n];
            inv = 1.0f / fmaxf(c, 1.0f);
            cc  = (c > 0.f) ? 1.f : 0.f;
        }
        inv_s[tid] = inv;
        cc_s[tid]  = cc;
    }
    if (tid < 128) {
        bmu_s[tid] = g_bmu[tid];
        bu_s[tid]  = bu[tid];
    }
    __syncthreads();

    // ---- global tile load into regs ----
    const int arow = tid >> 2, aq = tid & 3;          // A: 4 thr/row, 8 floats ea
    const int bn   = tid >> 1, bh2 = tid & 1;         // B: 2 thr/row, 16 bf16 ea
    auto load_regs = [&](int kb, float4 fA[2], uint4 bhv[2], uint4 blv[2], float& sc) {
        int r  = r0 + arow;
        int rc = (r < M_) ? r : (M_ - 1);
        int ph = kb >> 7;                             // 0:XS 1:x 2:EA
        const float* ap;
        if (ph == 0)      { ap = g_XS + (size_t)rc * 128; sc = inv_s[arow]; }
        else if (ph == 1) { ap = x    + (size_t)rc * 128; sc = cc_s[arow]; }
        else {
            int nn = (rc >= N_) ? (rc - N_) : rc;
            ap = g_EA + (size_t)nn * 128; sc = inv_s[arow];
        }
        ap += (kb & 127) + aq * 8;
        fA[0] = reinterpret_cast<const float4*>(ap)[0];
        fA[1] = reinterpret_cast<const float4*>(ap)[1];
        const __nv_bfloat16* bhp = g_Bhi + (size_t)bn * K_ + kb + bh2 * 16;
        const __nv_bfloat16* blp = g_Blo + (size_t)bn * K_ + kb + bh2 * 16;
        bhv[0] = reinterpret_cast<const uint4*>(bhp)[0];
        bhv[1] = reinterpret_cast<const uint4*>(bhp)[1];
        blv[0] = reinterpret_cast<const uint4*>(blp)[0];
        blv[1] = reinterpret_cast<const uint4*>(blp)[1];
    };
    auto store_tile = [&](int bf, float4 fA[2], uint4 bhv[2], uint4 blv[2], float sc) {
        fA[0].x *= sc; fA[0].y *= sc; fA[0].z *= sc; fA[0].w *= sc;
        fA[1].x *= sc; fA[1].y *= sc; fA[1].z *= sc; fA[1].w *= sc;
        uint4 h, l;
        split8(fA[0], fA[1], h, l);
        int aoff = (arow * STR_ + aq * 8) * 2;
        *reinterpret_cast<uint4*>(sm + AH_OFF + bf * ASZ_ + aoff) = h;
        *reinterpret_cast<uint4*>(sm + AL_OFF + bf * ASZ_ + aoff) = l;
        int boff = (bn * STR_ + bh2 * 16) * 2;
        uint4* dh = reinterpret_cast<uint4*>(sm + BH_OFF + bf * BSZ_ + boff);
        uint4* dl = reinterpret_cast<uint4*>(sm + BL_OFF + bf * BSZ_ + boff);
        dh[0] = bhv[0]; dh[1] = bhv[1];
        dl[0] = blv[0]; dl[1] = blv[1];
    };

    float acc[2][4][4];
    #pragma unroll
    for (int i = 0; i < 2; ++i)
        #pragma unroll
        for (int j = 0; j < 4; ++j)
            #pragma unroll
            for (int c = 0; c < 4; ++c) acc[i][j][c] = 0.f;

    // prologue
    {
        float4 fA[2]; uint4 bhv[2], blv[2]; float sc;
        load_regs(0, fA, bhv, blv, sc);
        store_tile(0, fA, bhv, blv, sc);
    }
    __syncthreads();

    const int NT = K_ / 32;  // 12
    for (int kt = 0; kt < NT; ++kt) {
        const int cur = kt & 1;

        float4 fA[2]; uint4 bhv[2], blv[2]; float sc = 0.f;
        if (kt + 1 < NT) load_regs((kt + 1) * 32, fA, bhv, blv, sc);

        const char* Ahb = sm + AH_OFF + cur * ASZ_;
        const char* Alb = sm + AL_OFF + cur * ASZ_;
        const char* Bhb = sm + BH_OFF + cur * BSZ_;
        const char* Blb = sm + BL_OFF + cur * BSZ_;

        #pragma unroll
        for (int ks = 0; ks < 2; ++ks) {
            const int k0 = ks * 16;
            uint32_t ah[2][4], al[2][4], bh[4][2], bl[4][2];
            #pragma unroll
            for (int i = 0; i < 2; ++i) {
                int base = ((wm * 32 + i * 16 + g) * STR_ + k0 + tq * 2) * 2;
                ah[i][0] = *reinterpret_cast<const uint32_t*>(Ahb + base);
                ah[i][1] = *reinterpret_cast<const uint32_t*>(Ahb + base + 8 * STR_ * 2);
                ah[i][2] = *reinterpret_cast<const uint32_t*>(Ahb + base + 16);
                ah[i][3] = *reinterpret_cast<const uint32_t*>(Ahb + base + 8 * STR_ * 2 + 16);
                al[i][0] = *reinterpret_cast<const uint32_t*>(Alb + base);
                al[i][1] = *reinterpret_cast<const uint32_t*>(Alb + base + 8 * STR_ * 2);
                al[i][2] = *reinterpret_cast<const uint32_t*>(Alb + base + 16);
                al[i][3] = *reinterpret_cast<const uint32_t*>(Alb + base + 8 * STR_ * 2 + 16);
            }
            #pragma unroll
            for (int j = 0; j < 4; ++j) {
                int nb = ((wn * 32 + j * 8 + g) * STR_ + k0 + tq * 2) * 2;
                bh[j][0] = *reinterpret_cast<const uint32_t*>(Bhb + nb);
                bh[j][1] = *reinterpret_cast<const uint32_t*>(Bhb + nb + 16);
                bl[j][0] = *reinterpret_cast<const uint32_t*>(Blb + nb);
                bl[j][1] = *reinterpret_cast<const uint32_t*>(Blb + nb + 16);
            }
            #pragma unroll
            for (int i = 0; i < 2; ++i)
                #pragma unroll
                for (int j = 0; j < 4; ++j) {
                    MMA_BF16(acc[i][j], ah[i], bh[j]);   // Ah*Bh
                    MMA_BF16(acc[i][j], ah[i], bl[j]);   // Ah*Bl
                    MMA_BF16(acc[i][j], al[i], bh[j]);   // Al*Bh
                }
        }

        if (kt + 1 < NT) store_tile(cur ^ 1, fA, bhv, blv, sc);
        __syncthreads();
    }

    // ---- epilogue ----
    #pragma unroll
    for (int i = 0; i < 2; ++i) {
        #pragma unroll
        for (int half = 0; half < 2; ++half) {
            int lrow = wm * 32 + i * 16 + g + half * 8;
            int r    = r0 + lrow;
            if (r < M_) {
                float ccf = cc_s[lrow];
                #pragma unroll
                for (int j = 0; j < 4; ++j) {
                    int c0 = wn * 32 + j * 8 + tq * 2;
                    float2 v;
                    v.x = acc[i][j][half * 2 + 0] + ccf * bmu_s[c0 + 0] + bu_s[c0 + 0];
                    v.y = acc[i][j][half * 2 + 1] + ccf * bmu_s[c0 + 1] + bu_s[c0 + 1];
                    *reinterpret_cast<float2*>(&out[(size_t)r * 128 + c0]) = v;
                }
            }
        }
    }
}

// ---------------------------------------------------------------------------
// Launch
// ---------------------------------------------------------------------------
extern "C" void kernel_launch(void* const* d_in, const int* in_sizes, int n_in,
                              void* d_out, int out_size) {
    const float* x  = (const float*)d_in[0];   // (B, N, D)
    const int*   ei = (const int*)  d_in[1];   // (2, E)
    const float* ea = (const float*)d_in[2];   // (E, D)
    const float* Wm = (const float*)d_in[3];   // (3D, O)
    const float* bm = (const float*)d_in[4];   // (O,)
    const float* Wu = (const float*)d_in[5];   // (O, O)
    const float* bu = (const float*)d_in[6];   // (O,)
    float* out = (float*)d_out;                // (B, N, O)

    cudaFuncSetAttribute(fused_gemm_mma,
                         cudaFuncAttributeMaxDynamicSharedMemorySize, SMEM_DYN_);

    zero_icnt<<<(N_ + 255) / 256, 256>>>();
    hist_kernel<<<(E_ + 255) / 256, 256>>>(ei);
    scan_kernel<<<1, 1024>>>();
    fill_kernel<<<(E_ + 255) / 256, 256>>>(ei);
    combine_weights<<<(K_ * O_ + 255) / 256, 256>>>(Wm, Wu, bm);
    aggregate<<<(int)(((size_t)N_ * 32 + 255) / 256), 256>>>(x, ea);
    fused_gemm_mma<<<(M_ + 63) / 64, 256, SMEM_DYN_>>>(x, bu, out);
}

// round 6
// speedup vs baseline: 1.2612x; 1.0530x over previous
#include <cuda_runtime.h>
#include <cuda_fp16.h>
#include <cstdint>
#include <cstddef>

#define B_ 2
#define N_ 50000
#define E_ 500000
#define D_ 128
#define O_ 128
#define K_ 384
#define M_ (B_*N_)

// ---------------------------------------------------------------------------
// Device scratch (no allocation allowed in kernel_launch)
// ---------------------------------------------------------------------------
__device__ float g_XS[(size_t)B_ * N_ * D_];   // per-dst sum of x[b, src]
__device__ float g_EA[(size_t)N_ * D_];        // per-dst sum of edge_attr
__device__ int   g_icnt[N_];                   // in-degree counts
__device__ int   g_off[N_ + 1];                // CSR offsets by dst
__device__ int   g_pos[N_];                    // fill cursor
__device__ int2  g_edge[E_];                   // (src, edge id) sorted by dst
__device__ __half g_Bhi[O_ * K_];              // (W_msg@W_upd)^T hi, [n][k]
__device__ __half g_Blo[O_ * K_];              // (W_msg@W_upd)^T lo (residual)
__device__ float g_bmu[O_];                    // b_msg @ W_upd

// ---------------------------------------------------------------------------
// mma.sync fp16 (sm_80-era PTX — compiles on plain compute_103)
// acc(f32x4) += A(16x16 fp16, 4 regs) @ B(16x8 fp16, 2 regs)
// ---------------------------------------------------------------------------
#define MMA_F16(d, a, b)                                                      \
    asm volatile("mma.sync.aligned.m16n8k16.row.col.f32.f16.f16.f32 "         \
        "{%0,%1,%2,%3}, {%4,%5,%6,%7}, {%8,%9}, {%0,%1,%2,%3};"               \
        : "+f"((d)[0]), "+f"((d)[1]), "+f"((d)[2]), "+f"((d)[3])              \
        : "r"((a)[0]), "r"((a)[1]), "r"((a)[2]), "r"((a)[3]),                 \
          "r"((b)[0]), "r"((b)[1]))

// Convert 8 fp32 (two float4) into packed fp16 (uint4).
__device__ __forceinline__ uint4 cvt8_h(float4 f0, float4 f1) {
    uint32_t p0, p1, p2, p3;
    asm("cvt.rn.f16x2.f32 %0, %2, %1;" : "=r"(p0) : "f"(f0.x), "f"(f0.y));
    asm("cvt.rn.f16x2.f32 %0, %2, %1;" : "=r"(p1) : "f"(f0.z), "f"(f0.w));
    asm("cvt.rn.f16x2.f32 %0, %2, %1;" : "=r"(p2) : "f"(f1.x), "f"(f1.y));
    asm("cvt.rn.f16x2.f32 %0, %2, %1;" : "=r"(p3) : "f"(f1.z), "f"(f1.w));
    return make_uint4(p0, p1, p2, p3);
}

// ---------------------------------------------------------------------------
// CSR build: histogram -> scan -> bucket fill (unchanged)
// ---------------------------------------------------------------------------
__global__ void zero_icnt() {
    int i = blockIdx.x * blockDim.x + threadIdx.x;
    if (i < N_) g_icnt[i] = 0;
}

__global__ void hist_kernel(const int* __restrict__ ei) {
    int e = blockIdx.x * blockDim.x + threadIdx.x;
    if (e < E_) atomicAdd(&g_icnt[ei[E_ + e]], 1);
}

__global__ void scan_kernel() {
    __shared__ int ssum[1024];
    const int CH = (N_ + 1023) / 1024;
    int t = threadIdx.x;
    int beg = t * CH, end = min(beg + CH, N_);
    int s = 0;
    for (int i = beg; i < end; ++i) s += g_icnt[i];
    ssum[t] = s;
    __syncthreads();
    for (int off = 1; off < 1024; off <<= 1) {
        int v = (t >= off) ? ssum[t - off] : 0;
        __syncthreads();
        ssum[t] += v;
        __syncthreads();
    }
    int run = (t == 0) ? 0 : ssum[t - 1];
    for (int i = beg; i < end; ++i) {
        g_off[i] = run;
        g_pos[i] = run;
        run += g_icnt[i];
    }
    if (t == 1023) g_off[N_] = run;
}

__global__ void fill_kernel(const int* __restrict__ ei) {
    int e = blockIdx.x * blockDim.x + threadIdx.x;
    if (e < E_) {
        int dst = ei[E_ + e];
        int p = atomicAdd(&g_pos[dst], 1);
        g_edge[p] = make_int2(ei[e], e);
    }
}

// ---------------------------------------------------------------------------
// Gather-sum aggregation (unchanged)
// ---------------------------------------------------------------------------
__global__ void aggregate(const float* __restrict__ x,
                          const float* __restrict__ ea) {
    int n = (int)(((size_t)blockIdx.x * blockDim.x + threadIdx.x) >> 5);
    int lane = threadIdx.x & 31;
    if (n >= N_) return;

    int j0 = g_off[n], j1 = g_off[n + 1];
    float4 aea = make_float4(0.f, 0.f, 0.f, 0.f);
    float4 ax0 = aea, ax1 = aea;
    float4 bea = aea, bx0 = aea, bx1 = aea;

    int j = j0;
    for (; j + 2 <= j1; j += 2) {
        int2 p0 = g_edge[j];
        int2 p1 = g_edge[j + 1];
        float4 va0 = reinterpret_cast<const float4*>(ea + (size_t)p0.y * D_)[lane];
        float4 va1 = reinterpret_cast<const float4*>(ea + (size_t)p1.y * D_)[lane];
        float4 u0  = reinterpret_cast<const float4*>(x + (size_t)p0.x * D_)[lane];
        float4 u1  = reinterpret_cast<const float4*>(x + (size_t)p1.x * D_)[lane];
        float4 w0  = reinterpret_cast<const float4*>(x + ((size_t)N_ + p0.x) * D_)[lane];
        float4 w1  = reinterpret_cast<const float4*>(x + ((size_t)N_ + p1.x) * D_)[lane];
        aea.x += va0.x; aea.y += va0.y; aea.z += va0.z; aea.w += va0.w;
        bea.x += va1.x; bea.y += va1.y; bea.z += va1.z; bea.w += va1.w;
        ax0.x += u0.x;  ax0.y += u0.y;  ax0.z += u0.z;  ax0.w += u0.w;
        bx0.x += u1.x;  bx0.y += u1.y;  bx0.z += u1.z;  bx0.w += u1.w;
        ax1.x += w0.x;  ax1.y += w0.y;  ax1.z += w0.z;  ax1.w += w0.w;
        bx1.x += w1.x;  bx1.y += w1.y;  bx1.z += w1.z;  bx1.w += w1.w;
    }
    if (j < j1) {
        int2 p0 = g_edge[j];
        float4 va = reinterpret_cast<const float4*>(ea + (size_t)p0.y * D_)[lane];
        float4 u  = reinterpret_cast<const float4*>(x + (size_t)p0.x * D_)[lane];
        float4 w  = reinterpret_cast<const float4*>(x + ((size_t)N_ + p0.x) * D_)[lane];
        aea.x += va.x; aea.y += va.y; aea.z += va.z; aea.w += va.w;
        ax0.x += u.x;  ax0.y += u.y;  ax0.z += u.z;  ax0.w += u.w;
        ax1.x += w.x;  ax1.y += w.y;  ax1.z += w.z;  ax1.w += w.w;
    }
    aea.x += bea.x; aea.y += bea.y; aea.z += bea.z; aea.w += bea.w;
    ax0.x += bx0.x; ax0.y += bx0.y; ax0.z += bx0.z; ax0.w += bx0.w;
    ax1.x += bx1.x; ax1.y += bx1.y; ax1.z += bx1.z; ax1.w += bx1.w;

    reinterpret_cast<float4*>(g_EA + (size_t)n * D_)[lane] = aea;
    reinterpret_cast<float4*>(g_XS + (size_t)n * D_)[lane] = ax0;
    reinterpret_cast<float4*>(g_XS + ((size_t)N_ + n) * D_)[lane] = ax1;
}

// ---------------------------------------------------------------------------
// Combined weights, transposed + fp16 hi/lo split:
//   Wc[k][o] = sum_j Wm[k][j]*Wu[j][o];  g_Bhi/lo[o][k] = splitf16(Wc[k][o])
// ---------------------------------------------------------------------------
__global__ void combine_weights(const float* __restrict__ Wm,
                                const float* __restrict__ Wu,
                                const float* __restrict__ bm) {
    int idx = blockIdx.x * blockDim.x + threadIdx.x;
    if (idx < K_ * O_) {
        int o = idx / K_;
        int k = idx - o * K_;
        float s = 0.f;
        #pragma unroll 8
        for (int j = 0; j < O_; ++j)
            s = fmaf(Wm[k * O_ + j], Wu[j * O_ + o], s);
        __half hb = __float2half_rn(s);
        float r = s - __half2float(hb);
        g_Bhi[idx] = hb;
        g_Blo[idx] = __float2half_rn(r);
    }
    if (idx < O_) {
        float s = 0.f;
        for (int j = 0; j < O_; ++j)
            s = fmaf(bm[j], Wu[j * O_ + idx], s);
        g_bmu[idx] = s;
    }
}

// ---------------------------------------------------------------------------
// Tensor-core fused GEMM via mma.sync fp16, 2 passes (A unsplit, B hi/lo):
//   out ≈ Ah@(Bh) + Ah@(Bl);  dropped Al@B ~ 2^-11 rel << 1e-3 gate.
// CTA tile 64x128, BK=32, 256 thr (8 warps = 2(m)x4(n)), warp tile 32x32.
// Smem rows padded to 40 fp16 -> conflict-free .b32 frag loads.
// ---------------------------------------------------------------------------
#define STR_ 40                       // fp16 per smem row
#define ASZ_ (64 * STR_ * 2)          // bytes per A buffer (5120)
#define BSZ_ (128 * STR_ * 2)         // bytes per B buffer (10240)
#define AH_OFF 0
#define BH_OFF (2 * ASZ_)             // 10240
#define BL_OFF (2 * ASZ_ + 2 * BSZ_)  // 30720
#define SMEM_DYN_ (2 * ASZ_ + 4 * BSZ_)  // 51200

__global__ __launch_bounds__(256)
void fused_gemm_mma(const float* __restrict__ x,
                    const float* __restrict__ bu,
                    float* __restrict__ out)
{
    extern __shared__ char sm[];
    __shared__ float inv_s[64], cc_s[64], bmu_s[128], bu_s[128];

    const int tid  = threadIdx.x;
    const int lane = tid & 31;
    const int wid  = tid >> 5;
    const int r0   = blockIdx.x * 64;
    const int wm   = wid >> 2;        // 0..1
    const int wn   = wid & 3;         // 0..3
    const int g    = lane >> 2;       // 0..7
    const int tq   = lane & 3;        // 0..3

    if (tid < 64) {
        int r = r0 + tid;
        float inv = 0.f, cc = 0.f;
        if (r < M_) {
            int n = (r >= N_) ? (r - N_) : r;
            float c = (float)g_icnt[n];
            inv = 1.0f / fmaxf(c, 1.0f);
            cc  = (c > 0.f) ? 1.f : 0.f;
        }
        inv_s[tid] = inv;
        cc_s[tid]  = cc;
    }
    if (tid < 128) {
        bmu_s[tid] = g_bmu[tid];
        bu_s[tid]  = bu[tid];
    }
    __syncthreads();

    // ---- global tile load into regs ----
    const int arow = tid >> 2, aq = tid & 3;          // A: 4 thr/row, 8 floats ea
    const int bn   = tid >> 1, bh2 = tid & 1;         // B: 2 thr/row, 16 fp16 ea
    auto load_regs = [&](int kb, float4 fA[2], uint4 bhv[2], uint4 blv[2], float& sc) {
        int r  = r0 + arow;
        int rc = (r < M_) ? r : (M_ - 1);
        int ph = kb >> 7;                             // 0:XS 1:x 2:EA
        const float* ap;
        if (ph == 0)      { ap = g_XS + (size_t)rc * 128; sc = inv_s[arow]; }
        else if (ph == 1) { ap = x    + (size_t)rc * 128; sc = cc_s[arow]; }
        else {
            int nn = (rc >= N_) ? (rc - N_) : rc;
            ap = g_EA + (size_t)nn * 128; sc = inv_s[arow];
        }
        ap += (kb & 127) + aq * 8;
        fA[0] = reinterpret_cast<const float4*>(ap)[0];
        fA[1] = reinterpret_cast<const float4*>(ap)[1];
        const __half* bhp = g_Bhi + (size_t)bn * K_ + kb + bh2 * 16;
        const __half* blp = g_Blo + (size_t)bn * K_ + kb + bh2 * 16;
        bhv[0] = reinterpret_cast<const uint4*>(bhp)[0];
        bhv[1] = reinterpret_cast<const uint4*>(bhp)[1];
        blv[0] = reinterpret_cast<const uint4*>(blp)[0];
        blv[1] = reinterpret_cast<const uint4*>(blp)[1];
    };
    auto store_tile = [&](int bf, float4 fA[2], uint4 bhv[2], uint4 blv[2], float sc) {
        fA[0].x *= sc; fA[0].y *= sc; fA[0].z *= sc; fA[0].w *= sc;
        fA[1].x *= sc; fA[1].y *= sc; fA[1].z *= sc; fA[1].w *= sc;
        uint4 h = cvt8_h(fA[0], fA[1]);
        int aoff = (arow * STR_ + aq * 8) * 2;
        *reinterpret_cast<uint4*>(sm + AH_OFF + bf * ASZ_ + aoff) = h;
        int boff = (bn * STR_ + bh2 * 16) * 2;
        uint4* dh = reinterpret_cast<uint4*>(sm + BH_OFF + bf * BSZ_ + boff);
        uint4* dl = reinterpret_cast<uint4*>(sm + BL_OFF + bf * BSZ_ + boff);
        dh[0] = bhv[0]; dh[1] = bhv[1];
        dl[0] = blv[0]; dl[1] = blv[1];
    };

    float acc[2][4][4];
    #pragma unroll
    for (int i = 0; i < 2; ++i)
        #pragma unroll
        for (int j = 0; j < 4; ++j)
            #pragma unroll
            for (int c = 0; c < 4; ++c) acc[i][j][c] = 0.f;

    // prologue
    {
        float4 fA[2]; uint4 bhv[2], blv[2]; float sc;
        load_regs(0, fA, bhv, blv, sc);
        store_tile(0, fA, bhv, blv, sc);
    }
    __syncthreads();

    const int NT = K_ / 32;  // 12
    for (int kt = 0; kt < NT; ++kt) {
        const int cur = kt & 1;

        float4 fA[2]; uint4 bhv[2], blv[2]; float sc = 0.f;
        if (kt + 1 < NT) load_regs((kt + 1) * 32, fA, bhv, blv, sc);

        const char* Ahb = sm + AH_OFF + cur * ASZ_;
        const char* Bhb = sm + BH_OFF + cur * BSZ_;
        const char* Blb = sm + BL_OFF + cur * BSZ_;

        #pragma unroll
        for (int ks = 0; ks < 2; ++ks) {
            const int k0 = ks * 16;
            uint32_t ah[2][4], bh[4][2], bl[4][2];
            #pragma unroll
            for (int i = 0; i < 2; ++i) {
                int base = ((wm * 32 + i * 16 + g) * STR_ + k0 + tq * 2) * 2;
                ah[i][0] = *reinterpret_cast<const uint32_t*>(Ahb + base);
                ah[i][1] = *reinterpret_cast<const uint32_t*>(Ahb + base + 8 * STR_ * 2);
                ah[i][2] = *reinterpret_cast<const uint32_t*>(Ahb + base + 16);
                ah[i][3] = *reinterpret_cast<const uint32_t*>(Ahb + base + 8 * STR_ * 2 + 16);
            }
            #pragma unroll
            for (int j = 0; j < 4; ++j) {
                int nb = ((wn * 32 + j * 8 + g) * STR_ + k0 + tq * 2) * 2;
                bh[j][0] = *reinterpret_cast<const uint32_t*>(Bhb + nb);
                bh[j][1] = *reinterpret_cast<const uint32_t*>(Bhb + nb + 16);
                bl[j][0] = *reinterpret_cast<const uint32_t*>(Blb + nb);
                bl[j][1] = *reinterpret_cast<const uint32_t*>(Blb + nb + 16);
            }
            #pragma unroll
            for (int i = 0; i < 2; ++i)
                #pragma unroll
                for (int j = 0; j < 4; ++j) {
                    MMA_F16(acc[i][j], ah[i], bh[j]);   // Ah*Bh
                    MMA_F16(acc[i][j], ah[i], bl[j]);   // Ah*Bl
                }
        }

        if (kt + 1 < NT) store_tile(cur ^ 1, fA, bhv, blv, sc);
        __syncthreads();
    }

    // ---- epilogue ----
    #pragma unroll
    for (int i = 0; i < 2; ++i) {
        #pragma unroll
        for (int half = 0; half < 2; ++half) {
            int lrow = wm * 32 + i * 16 + g + half * 8;
            int r    = r0 + lrow;
            if (r < M_) {
                float ccf = cc_s[lrow];
                #pragma unroll
                for (int j = 0; j < 4; ++j) {
                    int c0 = wn * 32 + j * 8 + tq * 2;
                    float2 v;
                    v.x = acc[i][j][half * 2 + 0] + ccf * bmu_s[c0 + 0] + bu_s[c0 + 0];
                    v.y = acc[i][j][half * 2 + 1] + ccf * bmu_s[c0 + 1] + bu_s[c0 + 1];
                    *reinterpret_cast<float2*>(&out[(size_t)r * 128 + c0]) = v;
                }
            }
        }
    }
}

// ---------------------------------------------------------------------------
// Launch
// ---------------------------------------------------------------------------
extern "C" void kernel_launch(void* const* d_in, const int* in_sizes, int n_in,
                              void* d_out, int out_size) {
    const float* x  = (const float*)d_in[0];   // (B, N, D)
    const int*   ei = (const int*)  d_in[1];   // (2, E)
    const float* ea = (const float*)d_in[2];   // (E, D)
    const float* Wm = (const float*)d_in[3];   // (3D, O)
    const float* bm = (const float*)d_in[4];   // (O,)
    const float* Wu = (const float*)d_in[5];   // (O, O)
    const float* bu = (const float*)d_in[6];   // (O,)
    float* out = (float*)d_out;                // (B, N, O)

    cudaFuncSetAttribute(fused_gemm_mma,
                         cudaFuncAttributeMaxDynamicSharedMemorySize, SMEM_DYN_);

    zero_icnt<<<(N_ + 255) / 256, 256>>>();
    hist_kernel<<<(E_ + 255) / 256, 256>>>(ei);
    scan_kernel<<<1, 1024>>>();
    fill_kernel<<<(E_ + 255) / 256, 256>>>(ei);
    combine_weights<<<(K_ * O_ + 255) / 256, 256>>>(Wm, Wu, bm);
    aggregate<<<(int)(((size_t)N_ * 32 + 255) / 256), 256>>>(x, ea);
    fused_gemm_mma<<<(M_ + 63) / 64, 256, SMEM_DYN_>>>(x, bu, out);
}

// round 7
// speedup vs baseline: 1.2972x; 1.0285x over previous
#include <cuda_runtime.h>
#include <cuda_fp16.h>
#include <cstdint>
#include <cstddef>

#define B_ 2
#define N_ 50000
#define E_ 500000
#define D_ 128
#define O_ 128
#define K_ 384
#define M_ (B_*N_)

// ---------------------------------------------------------------------------
// Device scratch (no allocation allowed in kernel_launch)
// ---------------------------------------------------------------------------
__device__ float g_XS[(size_t)B_ * N_ * D_];   // per-dst sum of x[b, src]
__device__ float g_EA[(size_t)N_ * D_];        // per-dst sum of edge_attr
__device__ __half g_xh[(size_t)B_ * N_ * D_];  // fp16 copy of x (25.6 MB)
__device__ int   g_icnt[N_];                   // in-degree counts
__device__ int   g_off[N_ + 1];                // CSR offsets by dst
__device__ int   g_pos[N_];                    // fill cursor
__device__ int2  g_edge[E_];                   // (src, edge id) sorted by dst
__device__ __half g_Bhi[O_ * K_];              // (W_msg@W_upd)^T hi, [n][k]
__device__ __half g_Blo[O_ * K_];              // (W_msg@W_upd)^T lo (residual)
__device__ float g_bmu[O_];                    // b_msg @ W_upd

// ---------------------------------------------------------------------------
// mma.sync fp16 (sm_80-era PTX — compiles on plain compute_103)
// ---------------------------------------------------------------------------
#define MMA_F16(d, a, b)                                                      \
    asm volatile("mma.sync.aligned.m16n8k16.row.col.f32.f16.f16.f32 "         \
        "{%0,%1,%2,%3}, {%4,%5,%6,%7}, {%8,%9}, {%0,%1,%2,%3};"               \
        : "+f"((d)[0]), "+f"((d)[1]), "+f"((d)[2]), "+f"((d)[3])              \
        : "r"((a)[0]), "r"((a)[1]), "r"((a)[2]), "r"((a)[3]),                 \
          "r"((b)[0]), "r"((b)[1]))

// Convert 8 fp32 (two float4) into packed fp16 (uint4).
__device__ __forceinline__ uint4 cvt8_h(float4 f0, float4 f1) {
    uint32_t p0, p1, p2, p3;
    asm("cvt.rn.f16x2.f32 %0, %2, %1;" : "=r"(p0) : "f"(f0.x), "f"(f0.y));
    asm("cvt.rn.f16x2.f32 %0, %2, %1;" : "=r"(p1) : "f"(f0.z), "f"(f0.w));
    asm("cvt.rn.f16x2.f32 %0, %2, %1;" : "=r"(p2) : "f"(f1.x), "f"(f1.y));
    asm("cvt.rn.f16x2.f32 %0, %2, %1;" : "=r"(p3) : "f"(f1.z), "f"(f1.w));
    return make_uint4(p0, p1, p2, p3);
}

// ---------------------------------------------------------------------------
// x -> fp16 copy (one uint4 = 8 values per thread)
// ---------------------------------------------------------------------------
__global__ void x_to_h(const float* __restrict__ x) {
    const size_t n8 = (size_t)B_ * N_ * D_ / 8;
    size_t i = (size_t)blockIdx.x * blockDim.x + threadIdx.x;
    if (i < n8) {
        float4 f0 = reinterpret_cast<const float4*>(x)[2 * i];
        float4 f1 = reinterpret_cast<const float4*>(x)[2 * i + 1];
        reinterpret_cast<uint4*>(g_xh)[i] = cvt8_h(f0, f1);
    }
}

// ---------------------------------------------------------------------------
// CSR build: histogram -> scan -> bucket fill (unchanged)
// ---------------------------------------------------------------------------
__global__ void zero_icnt() {
    int i = blockIdx.x * blockDim.x + threadIdx.x;
    if (i < N_) g_icnt[i] = 0;
}

__global__ void hist_kernel(const int* __restrict__ ei) {
    int e = blockIdx.x * blockDim.x + threadIdx.x;
    if (e < E_) atomicAdd(&g_icnt[ei[E_ + e]], 1);
}

__global__ void scan_kernel() {
    __shared__ int ssum[1024];
    const int CH = (N_ + 1023) / 1024;
    int t = threadIdx.x;
    int beg = t * CH, end = min(beg + CH, N_);
    int s = 0;
    for (int i = beg; i < end; ++i) s += g_icnt[i];
    ssum[t] = s;
    __syncthreads();
    for (int off = 1; off < 1024; off <<= 1) {
        int v = (t >= off) ? ssum[t - off] : 0;
        __syncthreads();
        ssum[t] += v;
        __syncthreads();
    }
    int run = (t == 0) ? 0 : ssum[t - 1];
    for (int i = beg; i < end; ++i) {
        g_off[i] = run;
        g_pos[i] = run;
        run += g_icnt[i];
    }
    if (t == 1023) g_off[N_] = run;
}

__global__ void fill_kernel(const int* __restrict__ ei) {
    int e = blockIdx.x * blockDim.x + threadIdx.x;
    if (e < E_) {
        int dst = ei[E_ + e];
        int p = atomicAdd(&g_pos[dst], 1);
        g_edge[p] = make_int2(ei[e], e);
    }
}

// ---------------------------------------------------------------------------
// Gather-sum aggregation: warp per node; x gathered as fp16 (256B rows),
// edge_attr as fp32 (512B rows); fp32 accumulation.
// ---------------------------------------------------------------------------
__device__ __forceinline__ void add_h4(float4& a, uint2 h) {
    float2 lo = __half22float2(*reinterpret_cast<__half2*>(&h.x));
    float2 hi = __half22float2(*reinterpret_cast<__half2*>(&h.y));
    a.x += lo.x; a.y += lo.y; a.z += hi.x; a.w += hi.y;
}

__global__ void aggregate(const float* __restrict__ ea) {
    int n = (int)(((size_t)blockIdx.x * blockDim.x + threadIdx.x) >> 5);
    int lane = threadIdx.x & 31;
    if (n >= N_) return;

    int j0 = g_off[n], j1 = g_off[n + 1];
    float4 aea = make_float4(0.f, 0.f, 0.f, 0.f);
    float4 ax0 = aea, ax1 = aea;
    float4 bea = aea, bx0 = aea, bx1 = aea;

    int j = j0;
    for (; j + 2 <= j1; j += 2) {
        int2 p0 = g_edge[j];
        int2 p1 = g_edge[j + 1];
        float4 va0 = reinterpret_cast<const float4*>(ea + (size_t)p0.y * D_)[lane];
        float4 va1 = reinterpret_cast<const float4*>(ea + (size_t)p1.y * D_)[lane];
        uint2 u0 = reinterpret_cast<const uint2*>(g_xh + (size_t)p0.x * D_)[lane];
        uint2 u1 = reinterpret_cast<const uint2*>(g_xh + (size_t)p1.x * D_)[lane];
        uint2 w0 = reinterpret_cast<const uint2*>(g_xh + ((size_t)N_ + p0.x) * D_)[lane];
        uint2 w1 = reinterpret_cast<const uint2*>(g_xh + ((size_t)N_ + p1.x) * D_)[lane];
        aea.x += va0.x; aea.y += va0.y; aea.z += va0.z; aea.w += va0.w;
        bea.x += va1.x; bea.y += va1.y; bea.z += va1.z; bea.w += va1.w;
        add_h4(ax0, u0); add_h4(bx0, u1);
        add_h4(ax1, w0); add_h4(bx1, w1);
    }
    if (j < j1) {
        int2 p0 = g_edge[j];
        float4 va = reinterpret_cast<const float4*>(ea + (size_t)p0.y * D_)[lane];
        uint2 u = reinterpret_cast<const uint2*>(g_xh + (size_t)p0.x * D_)[lane];
        uint2 w = reinterpret_cast<const uint2*>(g_xh + ((size_t)N_ + p0.x) * D_)[lane];
        aea.x += va.x; aea.y += va.y; aea.z += va.z; aea.w += va.w;
        add_h4(ax0, u);
        add_h4(ax1, w);
    }
    aea.x += bea.x; aea.y += bea.y; aea.z += bea.z; aea.w += bea.w;
    ax0.x += bx0.x; ax0.y += bx0.y; ax0.z += bx0.z; ax0.w += bx0.w;
    ax1.x += bx1.x; ax1.y += bx1.y; ax1.z += bx1.z; ax1.w += bx1.w;

    reinterpret_cast<float4*>(g_EA + (size_t)n * D_)[lane] = aea;
    reinterpret_cast<float4*>(g_XS + (size_t)n * D_)[lane] = ax0;
    reinterpret_cast<float4*>(g_XS + ((size_t)N_ + n) * D_)[lane] = ax1;
}

// ---------------------------------------------------------------------------
// Combined weights, transposed + fp16 hi/lo split (unchanged)
// ---------------------------------------------------------------------------
__global__ void combine_weights(const float* __restrict__ Wm,
                                const float* __restrict__ Wu,
                                const float* __restrict__ bm) {
    int idx = blockIdx.x * blockDim.x + threadIdx.x;
    if (idx < K_ * O_) {
        int o = idx / K_;
        int k = idx - o * K_;
        float s = 0.f;
        #pragma unroll 8
        for (int j = 0; j < O_; ++j)
            s = fmaf(Wm[k * O_ + j], Wu[j * O_ + o], s);
        __half hb = __float2half_rn(s);
        float r = s - __half2float(hb);
        g_Bhi[idx] = hb;
        g_Blo[idx] = __float2half_rn(r);
    }
    if (idx < O_) {
        float s = 0.f;
        for (int j = 0; j < O_; ++j)
            s = fmaf(bm[j], Wu[j * O_ + idx], s);
        g_bmu[idx] = s;
    }
}

// ---------------------------------------------------------------------------
// Tensor-core fused GEMM via mma.sync fp16, 2 passes (unchanged from R6)
// ---------------------------------------------------------------------------
#define STR_ 40                       // fp16 per smem row
#define ASZ_ (64 * STR_ * 2)          // bytes per A buffer (5120)
#define BSZ_ (128 * STR_ * 2)         // bytes per B buffer (10240)
#define AH_OFF 0
#define BH_OFF (2 * ASZ_)             // 10240
#define BL_OFF (2 * ASZ_ + 2 * BSZ_)  // 30720
#define SMEM_DYN_ (2 * ASZ_ + 4 * BSZ_)  // 51200

__global__ __launch_bounds__(256)
void fused_gemm_mma(const float* __restrict__ x,
                    const float* __restrict__ bu,
                    float* __restrict__ out)
{
    extern __shared__ char sm[];
    __shared__ float inv_s[64], cc_s[64], bmu_s[128], bu_s[128];

    const int tid  = threadIdx.x;
    const int lane = tid & 31;
    const int wid  = tid >> 5;
    const int r0   = blockIdx.x * 64;
    const int wm   = wid >> 2;        // 0..1
    const int wn   = wid & 3;         // 0..3
    const int g    = lane >> 2;       // 0..7
    const int tq   = lane & 3;        // 0..3

    if (tid < 64) {
        int r = r0 + tid;
        float inv = 0.f, cc = 0.f;
        if (r < M_) {
            int n = (r >= N_) ? (r - N_) : r;
            float c = (float)g_icnt[n];
            inv = 1.0f / fmaxf(c, 1.0f);
            cc  = (c > 0.f) ? 1.f : 0.f;
        }
        inv_s[tid] = inv;
        cc_s[tid]  = cc;
    }
    if (tid < 128) {
        bmu_s[tid] = g_bmu[tid];
        bu_s[tid]  = bu[tid];
    }
    __syncthreads();

    const int arow = tid >> 2, aq = tid & 3;          // A: 4 thr/row, 8 floats ea
    const int bn   = tid >> 1, bh2 = tid & 1;         // B: 2 thr/row, 16 fp16 ea
    auto load_regs = [&](int kb, float4 fA[2], uint4 bhv[2], uint4 blv[2], float& sc) {
        int r  = r0 + arow;
        int rc = (r < M_) ? r : (M_ - 1);
        int ph = kb >> 7;                             // 0:XS 1:x 2:EA
        const float* ap;
        if (ph == 0)      { ap = g_XS + (size_t)rc * 128; sc = inv_s[arow]; }
        else if (ph == 1) { ap = x    + (size_t)rc * 128; sc = cc_s[arow]; }
        else {
            int nn = (rc >= N_) ? (rc - N_) : rc;
            ap = g_EA + (size_t)nn * 128; sc = inv_s[arow];
        }
        ap += (kb & 127) + aq * 8;
        fA[0] = reinterpret_cast<const float4*>(ap)[0];
        fA[1] = reinterpret_cast<const float4*>(ap)[1];
        const __half* bhp = g_Bhi + (size_t)bn * K_ + kb + bh2 * 16;
        const __half* blp = g_Blo + (size_t)bn * K_ + kb + bh2 * 16;
        bhv[0] = reinterpret_cast<const uint4*>(bhp)[0];
        bhv[1] = reinterpret_cast<const uint4*>(bhp)[1];
        blv[0] = reinterpret_cast<const uint4*>(blp)[0];
        blv[1] = reinterpret_cast<const uint4*>(blp)[1];
    };
    auto store_tile = [&](int bf, float4 fA[2], uint4 bhv[2], uint4 blv[2], float sc) {
        fA[0].x *= sc; fA[0].y *= sc; fA[0].z *= sc; fA[0].w *= sc;
        fA[1].x *= sc; fA[1].y *= sc; fA[1].z *= sc; fA[1].w *= sc;
        uint4 h = cvt8_h(fA[0], fA[1]);
        int aoff = (arow * STR_ + aq * 8) * 2;
        *reinterpret_cast<uint4*>(sm + AH_OFF + bf * ASZ_ + aoff) = h;
        int boff = (bn * STR_ + bh2 * 16) * 2;
        uint4* dh = reinterpret_cast<uint4*>(sm + BH_OFF + bf * BSZ_ + boff);
        uint4* dl = reinterpret_cast<uint4*>(sm + BL_OFF + bf * BSZ_ + boff);
        dh[0] = bhv[0]; dh[1] = bhv[1];
        dl[0] = blv[0]; dl[1] = blv[1];
    };

    float acc[2][4][4];
    #pragma unroll
    for (int i = 0; i < 2; ++i)
        #pragma unroll
        for (int j = 0; j < 4; ++j)
            #pragma unroll
            for (int c = 0; c < 4; ++c) acc[i][j][c] = 0.f;

    {
        float4 fA[2]; uint4 bhv[2], blv[2]; float sc;
        load_regs(0, fA, bhv, blv, sc);
        store_tile(0, fA, bhv, blv, sc);
    }
    __syncthreads();

    const int NT = K_ / 32;  // 12
    for (int kt = 0; kt < NT; ++kt) {
        const int cur = kt & 1;

        float4 fA[2]; uint4 bhv[2], blv[2]; float sc = 0.f;
        if (kt + 1 < NT) load_regs((kt + 1) * 32, fA, bhv, blv, sc);

        const char* Ahb = sm + AH_OFF + cur * ASZ_;
        const char* Bhb = sm + BH_OFF + cur * BSZ_;
        const char* Blb = sm + BL_OFF + cur * BSZ_;

        #pragma unroll
        for (int ks = 0; ks < 2; ++ks) {
            const int k0 = ks * 16;
            uint32_t ah[2][4], bh[4][2], bl[4][2];
            #pragma unroll
            for (int i = 0; i < 2; ++i) {
                int base = ((wm * 32 + i * 16 + g) * STR_ + k0 + tq * 2) * 2;
                ah[i][0] = *reinterpret_cast<const uint32_t*>(Ahb + base);
                ah[i][1] = *reinterpret_cast<const uint32_t*>(Ahb + base + 8 * STR_ * 2);
                ah[i][2] = *reinterpret_cast<const uint32_t*>(Ahb + base + 16);
                ah[i][3] = *reinterpret_cast<const uint32_t*>(Ahb + base + 8 * STR_ * 2 + 16);
            }
            #pragma unroll
            for (int j = 0; j < 4; ++j) {
                int nb = ((wn * 32 + j * 8 + g) * STR_ + k0 + tq * 2) * 2;
                bh[j][0] = *reinterpret_cast<const uint32_t*>(Bhb + nb);
                bh[j][1] = *reinterpret_cast<const uint32_t*>(Bhb + nb + 16);
                bl[j][0] = *reinterpret_cast<const uint32_t*>(Blb + nb);
                bl[j][1] = *reinterpret_cast<const uint32_t*>(Blb + nb + 16);
            }
            #pragma unroll
            for (int i = 0; i < 2; ++i)
                #pragma unroll
                for (int j = 0; j < 4; ++j) {
                    MMA_F16(acc[i][j], ah[i], bh[j]);   // Ah*Bh
                    MMA_F16(acc[i][j], ah[i], bl[j]);   // Ah*Bl
                }
        }

        if (kt + 1 < NT) store_tile(cur ^ 1, fA, bhv, blv, sc);
        __syncthreads();
    }

    #pragma unroll
    for (int i = 0; i < 2; ++i) {
        #pragma unroll
        for (int half = 0; half < 2; ++half) {
            int lrow = wm * 32 + i * 16 + g + half * 8;
            int r    = r0 + lrow;
            if (r < M_) {
                float ccf = cc_s[lrow];
                #pragma unroll
                for (int j = 0; j < 4; ++j) {
                    int c0 = wn * 32 + j * 8 + tq * 2;
                    float2 v;
                    v.x = acc[i][j][half * 2 + 0] + ccf * bmu_s[c0 + 0] + bu_s[c0 + 0];
                    v.y = acc[i][j][half * 2 + 1] + ccf * bmu_s[c0 + 1] + bu_s[c0 + 1];
                    *reinterpret_cast<float2*>(&out[(size_t)r * 128 + c0]) = v;
                }
            }
        }
    }
}

// ---------------------------------------------------------------------------
// Launch
// ---------------------------------------------------------------------------
extern "C" void kernel_launch(void* const* d_in, const int* in_sizes, int n_in,
                              void* d_out, int out_size) {
    const float* x  = (const float*)d_in[0];   // (B, N, D)
    const int*   ei = (const int*)  d_in[1];   // (2, E)
    const float* ea = (const float*)d_in[2];   // (E, D)
    const float* Wm = (const float*)d_in[3];   // (3D, O)
    const float* bm = (const float*)d_in[4];   // (O,)
    const float* Wu = (const float*)d_in[5];   // (O, O)
    const float* bu = (const float*)d_in[6];   // (O,)
    float* out = (float*)d_out;                // (B, N, O)

    cudaFuncSetAttribute(fused_gemm_mma,
                         cudaFuncAttributeMaxDynamicSharedMemorySize, SMEM_DYN_);

    const size_t n8 = (size_t)B_ * N_ * D_ / 8;
    zero_icnt<<<(N_ + 255) / 256, 256>>>();
    hist_kernel<<<(E_ + 255) / 256, 256>>>(ei);
    scan_kernel<<<1, 1024>>>();
    fill_kernel<<<(E_ + 255) / 256, 256>>>(ei);
    x_to_h<<<(unsigned)((n8 + 255) / 256), 256>>>(x);
    combine_weights<<<(K_ * O_ + 255) / 256, 256>>>(Wm, Wu, bm);
    aggregate<<<(int)(((size_t)N_ * 32 + 255) / 256), 256>>>(ea);
    fused_gemm_mma<<<(M_ + 63) / 64, 256, SMEM_DYN_>>>(x, bu, out);
}

// round 8
// speedup vs baseline: 1.4766x; 1.1383x over previous
#include <cuda_runtime.h>
#include <cuda_fp16.h>
#include <cstdint>
#include <cstddef>

#define B_ 2
#define N_ 50000
#define E_ 500000
#define D_ 128
#define O_ 128
#define K_ 384
#define M_ (B_*N_)
#define MPAD_ (M_ + 128)

// ---------------------------------------------------------------------------
// Device scratch
// ---------------------------------------------------------------------------
__device__ __half g_A[(size_t)MPAD_ * K_];     // fp16 GEMM A: [inv*XS | cc*x | inv*EA] (76.9MB)
__device__ __half g_xh[(size_t)B_ * N_ * D_];  // fp16 copy of x (25.6 MB)
__device__ int   g_icnt[N_];                   // in-degree counts
__device__ int   g_off[N_ + 1];                // CSR offsets by dst
__device__ int   g_pos[N_];                    // fill cursor
__device__ int2  g_edge[E_];                   // (src, edge id) sorted by dst
__device__ __half g_Bhi[O_ * K_];              // (W_msg@W_upd)^T hi, [n][k]
__device__ __half g_Blo[O_ * K_];              // (W_msg@W_upd)^T lo (residual)
__device__ float g_bmu[O_];                    // b_msg @ W_upd

// ---------------------------------------------------------------------------
// PTX helpers
// ---------------------------------------------------------------------------
#define MMA_F16(d, a, b)                                                      \
    asm volatile("mma.sync.aligned.m16n8k16.row.col.f32.f16.f16.f32 "         \
        "{%0,%1,%2,%3}, {%4,%5,%6,%7}, {%8,%9}, {%0,%1,%2,%3};"               \
        : "+f"((d)[0]), "+f"((d)[1]), "+f"((d)[2]), "+f"((d)[3])              \
        : "r"((a)[0]), "r"((a)[1]), "r"((a)[2]), "r"((a)[3]),                 \
          "r"((b)[0]), "r"((b)[1]))

#define CP_ASYNC16(dst_u32, src_ptr)                                          \
    asm volatile("cp.async.cg.shared.global [%0], [%1], 16;"                  \
                 :: "r"(dst_u32), "l"(src_ptr))
#define CP_COMMIT() asm volatile("cp.async.commit_group;" ::: "memory")
#define CP_WAIT(n)  asm volatile("cp.async.wait_group %0;" :: "n"(n) : "memory")

__device__ __forceinline__ uint32_t smem_u32(const void* p) {
    uint32_t a;
    asm("{ .reg .u64 t; cvta.to.shared.u64 t, %1; cvt.u32.u64 %0, t; }"
        : "=r"(a) : "l"(p));
    return a;
}

__device__ __forceinline__ uint4 cvt8_h(float4 f0, float4 f1) {
    uint32_t p0, p1, p2, p3;
    asm("cvt.rn.f16x2.f32 %0, %2, %1;" : "=r"(p0) : "f"(f0.x), "f"(f0.y));
    asm("cvt.rn.f16x2.f32 %0, %2, %1;" : "=r"(p1) : "f"(f0.z), "f"(f0.w));
    asm("cvt.rn.f16x2.f32 %0, %2, %1;" : "=r"(p2) : "f"(f1.x), "f"(f1.y));
    asm("cvt.rn.f16x2.f32 %0, %2, %1;" : "=r"(p3) : "f"(f1.z), "f"(f1.w));
    return make_uint4(p0, p1, p2, p3);
}
__device__ __forceinline__ uint2 cvt4_h(float4 f) {
    uint32_t p0, p1;
    asm("cvt.rn.f16x2.f32 %0, %2, %1;" : "=r"(p0) : "f"(f.x), "f"(f.y));
    asm("cvt.rn.f16x2.f32 %0, %2, %1;" : "=r"(p1) : "f"(f.z), "f"(f.w));
    return make_uint2(p0, p1);
}

// ---------------------------------------------------------------------------
// x -> fp16 copy
// ---------------------------------------------------------------------------
__global__ void x_to_h(const float* __restrict__ x) {
    const size_t n8 = (size_t)B_ * N_ * D_ / 8;
    size_t i = (size_t)blockIdx.x * blockDim.x + threadIdx.x;
    if (i < n8) {
        float4 f0 = reinterpret_cast<const float4*>(x)[2 * i];
        float4 f1 = reinterpret_cast<const float4*>(x)[2 * i + 1];
        reinterpret_cast<uint4*>(g_xh)[i] = cvt8_h(f0, f1);
    }
}

// ---------------------------------------------------------------------------
// CSR build (unchanged)
// ---------------------------------------------------------------------------
__global__ void zero_icnt() {
    int i = blockIdx.x * blockDim.x + threadIdx.x;
    if (i < N_) g_icnt[i] = 0;
}

__global__ void hist_kernel(const int* __restrict__ ei) {
    int e = blockIdx.x * blockDim.x + threadIdx.x;
    if (e < E_) atomicAdd(&g_icnt[ei[E_ + e]], 1);
}

__global__ void scan_kernel() {
    __shared__ int ssum[1024];
    const int CH = (N_ + 1023) / 1024;
    int t = threadIdx.x;
    int beg = t * CH, end = min(beg + CH, N_);
    int s = 0;
    for (int i = beg; i < end; ++i) s += g_icnt[i];
    ssum[t] = s;
    __syncthreads();
    for (int off = 1; off < 1024; off <<= 1) {
        int v = (t >= off) ? ssum[t - off] : 0;
        __syncthreads();
        ssum[t] += v;
        __syncthreads();
    }
    int run = (t == 0) ? 0 : ssum[t - 1];
    for (int i = beg; i < end; ++i) {
        g_off[i] = run;
        g_pos[i] = run;
        run += g_icnt[i];
    }
    if (t == 1023) g_off[N_] = run;
}

__global__ void fill_kernel(const int* __restrict__ ei) {
    int e = blockIdx.x * blockDim.x + threadIdx.x;
    if (e < E_) {
        int dst = ei[E_ + e];
        int p = atomicAdd(&g_pos[dst], 1);
        g_edge[p] = make_int2(ei[e], e);
    }
}

// ---------------------------------------------------------------------------
// Aggregation: warp per node. Gathers x (fp16) + ea (fp32), fp32 accumulate,
// then writes the GEMM A rows DIRECTLY in fp16:
//   g_A[n]    = [ inv*XS(b0) | cc*x(b0,n) | inv*EA ]
//   g_A[N+n]  = [ inv*XS(b1) | cc*x(b1,n) | inv*EA ]
// ---------------------------------------------------------------------------
__device__ __forceinline__ void add_h4(float4& a, uint2 h) {
    float2 lo = __half22float2(*reinterpret_cast<__half2*>(&h.x));
    float2 hi = __half22float2(*reinterpret_cast<__half2*>(&h.y));
    a.x += lo.x; a.y += lo.y; a.z += hi.x; a.w += hi.y;
}
__device__ __forceinline__ float4 scale4(float4 a, float s) {
    return make_float4(a.x * s, a.y * s, a.z * s, a.w * s);
}

__global__ void aggregate(const float* __restrict__ ea) {
    int n = (int)(((size_t)blockIdx.x * blockDim.x + threadIdx.x) >> 5);
    int lane = threadIdx.x & 31;
    if (n >= N_) return;

    int j0 = g_off[n], j1 = g_off[n + 1];
    float4 aea = make_float4(0.f, 0.f, 0.f, 0.f);
    float4 ax0 = aea, ax1 = aea;
    float4 bea = aea, bx0 = aea, bx1 = aea;

    int j = j0;
    for (; j + 2 <= j1; j += 2) {
        int2 p0 = g_edge[j];
        int2 p1 = g_edge[j + 1];
        float4 va0 = reinterpret_cast<const float4*>(ea + (size_t)p0.y * D_)[lane];
        float4 va1 = reinterpret_cast<const float4*>(ea + (size_t)p1.y * D_)[lane];
        uint2 u0 = reinterpret_cast<const uint2*>(g_xh + (size_t)p0.x * D_)[lane];
        uint2 u1 = reinterpret_cast<const uint2*>(g_xh + (size_t)p1.x * D_)[lane];
        uint2 w0 = reinterpret_cast<const uint2*>(g_xh + ((size_t)N_ + p0.x) * D_)[lane];
        uint2 w1 = reinterpret_cast<const uint2*>(g_xh + ((size_t)N_ + p1.x) * D_)[lane];
        aea.x += va0.x; aea.y += va0.y; aea.z += va0.z; aea.w += va0.w;
        bea.x += va1.x; bea.y += va1.y; bea.z += va1.z; bea.w += va1.w;
        add_h4(ax0, u0); add_h4(bx0, u1);
        add_h4(ax1, w0); add_h4(bx1, w1);
    }
    if (j < j1) {
        int2 p0 = g_edge[j];
        float4 va = reinterpret_cast<const float4*>(ea + (size_t)p0.y * D_)[lane];
        uint2 u = reinterpret_cast<const uint2*>(g_xh + (size_t)p0.x * D_)[lane];
        uint2 w = reinterpret_cast<const uint2*>(g_xh + ((size_t)N_ + p0.x) * D_)[lane];
        aea.x += va.x; aea.y += va.y; aea.z += va.z; aea.w += va.w;
        add_h4(ax0, u);
        add_h4(ax1, w);
    }
    aea.x += bea.x; aea.y += bea.y; aea.z += bea.z; aea.w += bea.w;
    ax0.x += bx0.x; ax0.y += bx0.y; ax0.z += bx0.z; ax0.w += bx0.w;
    ax1.x += bx1.x; ax1.y += bx1.y; ax1.z += bx1.z; ax1.w += bx1.w;

    int deg = j1 - j0;
    float inv = 1.0f / (float)max(deg, 1);
    bool has = (deg > 0);

    // own-node x rows (cc * x)
    uint2 xc0 = make_uint2(0u, 0u), xc1 = xc0;
    if (has) {
        xc0 = reinterpret_cast<const uint2*>(g_xh + (size_t)n * D_)[lane];
        xc1 = reinterpret_cast<const uint2*>(g_xh + ((size_t)N_ + n) * D_)[lane];
    }

    __half* r0p = g_A + (size_t)n * K_;
    __half* r1p = g_A + ((size_t)N_ + n) * K_;
    uint2 eah = cvt4_h(scale4(aea, inv));
    reinterpret_cast<uint2*>(r0p)[lane]      = cvt4_h(scale4(ax0, inv));  // [0:128)
    reinterpret_cast<uint2*>(r0p + 128)[lane] = xc0;                      // [128:256)
    reinterpret_cast<uint2*>(r0p + 256)[lane] = eah;                      // [256:384)
    reinterpret_cast<uint2*>(r1p)[lane]      = cvt4_h(scale4(ax1, inv));
    reinterpret_cast<uint2*>(r1p + 128)[lane] = xc1;
    reinterpret_cast<uint2*>(r1p + 256)[lane] = eah;
}

// ---------------------------------------------------------------------------
// Combined weights, transposed + fp16 hi/lo split (unchanged)
// ---------------------------------------------------------------------------
__global__ void combine_weights(const float* __restrict__ Wm,
                                const float* __restrict__ Wu,
                                const float* __restrict__ bm) {
    int idx = blockIdx.x * blockDim.x + threadIdx.x;
    if (idx < K_ * O_) {
        int o = idx / K_;
        int k = idx - o * K_;
        float s = 0.f;
        #pragma unroll 8
        for (int j = 0; j < O_; ++j)
            s = fmaf(Wm[k * O_ + j], Wu[j * O_ + o], s);
        __half hb = __float2half_rn(s);
        float r = s - __half2float(hb);
        g_Bhi[idx] = hb;
        g_Blo[idx] = __float2half_rn(r);
    }
    if (idx < O_) {
        float s = 0.f;
        for (int j = 0; j < O_; ++j)
            s = fmaf(bm[j], Wu[j * O_ + idx], s);
        g_bmu[idx] = s;
    }
}

// ---------------------------------------------------------------------------
// HGEMM: out[M,128] = g_A[M,384] @ (Bhi+Blo)^T + cc*bmu + bu
// CTA tile 128x128, BK=32, 256 thr (8 warps = 4(m)x2(n)), warp tile 32x64.
// All tiles moved with cp.async (16B), double buffered.
// ---------------------------------------------------------------------------
#define STR_ 40                       // fp16 per smem row
#define TB_  (128 * STR_ * 2)         // bytes per tile buffer (10240)
#define AOF(bf)  ((bf) * TB_)
#define BHOF(bf) (2 * TB_ + (bf) * TB_)
#define BLOF(bf) (4 * TB_ + (bf) * TB_)
#define SMEM_DYN_ (6 * TB_)           // 61440

__global__ __launch_bounds__(256, 2)
void fused_gemm_mma(const float* __restrict__ bu,
                    float* __restrict__ out)
{
    extern __shared__ char sm[];
    __shared__ float cc_s[128], bmu_s[128], bu_s[128];

    const int tid  = threadIdx.x;
    const int lane = tid & 31;
    const int wid  = tid >> 5;
    const int r0   = blockIdx.x * 128;
    const int wm   = wid >> 1;        // 0..3
    const int wn   = wid & 1;         // 0..1
    const int g    = lane >> 2;       // 0..7
    const int tq   = lane & 3;        // 0..3

    const uint32_t smb = smem_u32(sm);

    if (tid < 128) {
        int r = r0 + tid;
        float cc = 0.f;
        if (r < M_) {
            int n = (r >= N_) ? (r - N_) : r;
            cc = (g_icnt[n] > 0) ? 1.f : 0.f;
        }
        cc_s[tid]  = cc;
        bmu_s[tid] = g_bmu[tid];
        bu_s[tid]  = bu[tid];
    }

    // cp.async issue for one k-tile: A, Bhi, Blo each 128 rows x 32 fp16.
    // 512 16B-chunks per matrix; 256 threads -> 2 chunks each.
    auto issue = [&](int kb, int bf) {
        #pragma unroll
        for (int t = 0; t < 2; ++t) {
            int c    = tid + t * 256;
            int row  = c >> 2;
            int col8 = (c & 3) * 8;               // fp16 offset within 32
            uint32_t so = (uint32_t)((row * STR_ + col8) * 2);
            const __half* asrc = g_A   + (size_t)(r0 + row) * K_ + kb + col8;
            const __half* hsrc = g_Bhi + (size_t)row * K_ + kb + col8;
            const __half* lsrc = g_Blo + (size_t)row * K_ + kb + col8;
            CP_ASYNC16(smb + AOF(bf)  + so, asrc);
            CP_ASYNC16(smb + BHOF(bf) + so, hsrc);
            CP_ASYNC16(smb + BLOF(bf) + so, lsrc);
        }
        CP_COMMIT();
    };

    float acc[2][8][4];
    #pragma unroll
    for (int i = 0; i < 2; ++i)
        #pragma unroll
        for (int j = 0; j < 8; ++j)
            #pragma unroll
            for (int c = 0; c < 4; ++c) acc[i][j][c] = 0.f;

    issue(0, 0);

    const int NT = K_ / 32;  // 12
    for (int kt = 0; kt < NT; ++kt) {
        const int cur = kt & 1;
        if (kt + 1 < NT) {
            issue((kt + 1) * 32, cur ^ 1);
            CP_WAIT(1);
        } else {
            CP_WAIT(0);
        }
        __syncthreads();

        const char* Ab  = sm + AOF(cur);
        const char* Bhb = sm + BHOF(cur);
        const char* Blb = sm + BLOF(cur);

        #pragma unroll
        for (int ks = 0; ks < 2; ++ks) {
            const int k0 = ks * 16;
            uint32_t ah[2][4], bh[8][2], bl[8][2];
            #pragma unroll
            for (int i = 0; i < 2; ++i) {
                int base = ((wm * 32 + i * 16 + g) * STR_ + k0 + tq * 2) * 2;
                ah[i][0] = *reinterpret_cast<const uint32_t*>(Ab + base);
                ah[i][1] = *reinterpret_cast<const uint32_t*>(Ab + base + 8 * STR_ * 2);
                ah[i][2] = *reinterpret_cast<const uint32_t*>(Ab + base + 16);
                ah[i][3] = *reinterpret_cast<const uint32_t*>(Ab + base + 8 * STR_ * 2 + 16);
            }
            #pragma unroll
            for (int j = 0; j < 8; ++j) {
                int nb = ((wn * 64 + j * 8 + g) * STR_ + k0 + tq * 2) * 2;
                bh[j][0] = *reinterpret_cast<const uint32_t*>(Bhb + nb);
                bh[j][1] = *reinterpret_cast<const uint32_t*>(Bhb + nb + 16);
                bl[j][0] = *reinterpret_cast<const uint32_t*>(Blb + nb);
                bl[j][1] = *reinterpret_cast<const uint32_t*>(Blb + nb + 16);
            }
            #pragma unroll
            for (int i = 0; i < 2; ++i)
                #pragma unroll
                for (int j = 0; j < 8; ++j) {
                    MMA_F16(acc[i][j], ah[i], bh[j]);
                    MMA_F16(acc[i][j], ah[i], bl[j]);
                }
        }
        __syncthreads();
    }

    // epilogue
    #pragma unroll
    for (int i = 0; i < 2; ++i) {
        #pragma unroll
        for (int half = 0; half < 2; ++half) {
            int lrow = wm * 32 + i * 16 + g + half * 8;
            int r    = r0 + lrow;
            if (r < M_) {
                float ccf = cc_s[lrow];
                #pragma unroll
                for (int j = 0; j < 8; ++j) {
                    int c0 = wn * 64 + j * 8 + tq * 2;
                    float2 v;
                    v.x = acc[i][j][half * 2 + 0] + ccf * bmu_s[c0 + 0] + bu_s[c0 + 0];
                    v.y = acc[i][j][half * 2 + 1] + ccf * bmu_s[c0 + 1] + bu_s[c0 + 1];
                    *reinterpret_cast<float2*>(&out[(size_t)r * 128 + c0]) = v;
                }
            }
        }
    }
}

// ---------------------------------------------------------------------------
// Launch
// ---------------------------------------------------------------------------
extern "C" void kernel_launch(void* const* d_in, const int* in_sizes, int n_in,
                              void* d_out, int out_size) {
    const float* x  = (const float*)d_in[0];   // (B, N, D)
    const int*   ei = (const int*)  d_in[1];   // (2, E)
    const float* ea = (const float*)d_in[2];   // (E, D)
    const float* Wm = (const float*)d_in[3];   // (3D, O)
    const float* bm = (const float*)d_in[4];   // (O,)
    const float* Wu = (const float*)d_in[5];   // (O, O)
    const float* bu = (const float*)d_in[6];   // (O,)
    float* out = (float*)d_out;                // (B, N, O)

    cudaFuncSetAttribute(fused_gemm_mma,
                         cudaFuncAttributeMaxDynamicSharedMemorySize, SMEM_DYN_);

    const size_t n8 = (size_t)B_ * N_ * D_ / 8;
    zero_icnt<<<(N_ + 255) / 256, 256>>>();
    hist_kernel<<<(E_ + 255) / 256, 256>>>(ei);
    scan_kernel<<<1, 1024>>>();
    fill_kernel<<<(E_ + 255) / 256, 256>>>(ei);
    x_to_h<<<(unsigned)((n8 + 255) / 256), 256>>>(x);
    combine_weights<<<(K_ * O_ + 255) / 256, 256>>>(Wm, Wu, bm);
    aggregate<<<(int)(((size_t)N_ * 32 + 255) / 256), 256>>>(ea);
    fused_gemm_mma<<<(M_ + 127) / 128, 256, SMEM_DYN_>>>(bu, out);
}